// round 3
// baseline (speedup 1.0000x reference)
#include <cuda_runtime.h>
#include <cstdint>

#define NNODES  50000
#define NEDGES  800000
#define NGRAPHS 256
#define SLOPE   0.01f

// ---------------- device scratch (no allocations allowed) ----------------
__device__ int   g_deg[NNODES];
__device__ int   g_fill[NNODES];
__device__ int   g_rowptr[NNODES + 1];
__device__ int   g_esrc[NEDGES];
__device__ float g_h0[NNODES * 3];
__device__ float g_buf1[(size_t)NNODES * 128];   // cols 0-63: h1, 64-127: aggr(h1)
__device__ float g_Y[(size_t)NNODES * 512];      // cols 0-255: orig@we_root, 256-511: orig@we_rel
__device__ float g_lat[(size_t)NNODES * 512];    // cols 0-255: latent, 256-511: aggr(latent)
__device__ float g_W2[128 * 1024];
__device__ float g_We[1024 * 512];
__device__ float g_Wd[512 * 1024];
__device__ float g_pooled[NGRAPHS * 256];
__device__ float g_counts[NGRAPHS];

__device__ __forceinline__ float lrelu(float v) { return v >= 0.f ? v : SLOPE * v; }

// ---------------- CSR build ----------------
__global__ void deg_kernel(const int* __restrict__ dst, int E) {
    int i = blockIdx.x * blockDim.x + threadIdx.x;
    if (i < E) atomicAdd(&g_deg[dst[i]], 1);
}

__global__ void scan_kernel() {
    __shared__ int sm[1024];
    const int CH = (NNODES + 1023) / 1024;
    int t = threadIdx.x;
    int base = t * CH;
    int s = 0;
    for (int i = 0; i < CH; i++) {
        int idx = base + i;
        if (idx < NNODES) s += g_deg[idx];
    }
    sm[t] = s;
    __syncthreads();
    for (int off = 1; off < 1024; off <<= 1) {
        int v = (t >= off) ? sm[t - off] : 0;
        __syncthreads();
        sm[t] += v;
        __syncthreads();
    }
    int prefix = (t > 0) ? sm[t - 1] : 0;
    for (int i = 0; i < CH; i++) {
        int idx = base + i;
        if (idx < NNODES) {
            g_rowptr[idx] = prefix;
            prefix += g_deg[idx];
        }
    }
    if (t == 0) g_rowptr[NNODES] = sm[1023];
}

__global__ void fill_kernel(const int* __restrict__ src, const int* __restrict__ dst, int E) {
    int i = blockIdx.x * blockDim.x + threadIdx.x;
    if (i < E) {
        int d = dst[i];
        int pos = atomicAdd(&g_fill[d], 1);
        g_esrc[g_rowptr[d] + pos] = src[i];
    }
}

// ---------------- embedding + conv1 (3 -> 64, fused) ----------------
__global__ void embed_kernel(const int* __restrict__ x, const float* __restrict__ emb) {
    int n = blockIdx.x * blockDim.x + threadIdx.x;
    if (n < NNODES) {
        int l = x[n];
        g_h0[n * 3 + 0] = emb[l * 3 + 0];
        g_h0[n * 3 + 1] = emb[l * 3 + 1];
        g_h0[n * 3 + 2] = emb[l * 3 + 2];
    }
}

__global__ void conv1_kernel(const float* __restrict__ w_rel, const float* __restrict__ w_root,
                             const float* __restrict__ b) {
    int gw = (blockIdx.x * blockDim.x + threadIdx.x) >> 5;
    int lane = threadIdx.x & 31;
    if (gw >= NNODES) return;
    float s0 = 0.f, s1 = 0.f, s2 = 0.f;
    int e0 = g_rowptr[gw], e1 = g_rowptr[gw + 1];
    for (int e = e0 + lane; e < e1; e += 32) {
        const float* h = &g_h0[3 * g_esrc[e]];
        s0 += h[0]; s1 += h[1]; s2 += h[2];
    }
#pragma unroll
    for (int off = 16; off; off >>= 1) {
        s0 += __shfl_xor_sync(0xffffffffu, s0, off);
        s1 += __shfl_xor_sync(0xffffffffu, s1, off);
        s2 += __shfl_xor_sync(0xffffffffu, s2, off);
    }
    float r0 = g_h0[gw * 3 + 0], r1 = g_h0[gw * 3 + 1], r2 = g_h0[gw * 3 + 2];
#pragma unroll
    for (int q = 0; q < 2; q++) {
        int j = lane + 32 * q;
        float v = b[j] + r0 * w_root[j] + r1 * w_root[64 + j] + r2 * w_root[128 + j]
                       + s0 * w_rel[j]  + s1 * w_rel[64 + j]  + s2 * w_rel[128 + j];
        g_buf1[(size_t)gw * 128 + j] = lrelu(v);
    }
}

// ---------------- generic warp-per-node CSR aggregation ----------------
// acc[c] = sum over in-edges of X[src][xoff + lane + 32c];
// out = (addY ? acc + addY-row : acc) (+ bias) (lrelu?) -> O[node][ooff + ...]
template <int CPL>
__global__ void agg_csr(const float* __restrict__ X, int ldx, int xoff,
                        float* __restrict__ O, int ldo, int ooff,
                        const float* __restrict__ addY, int ldy, int yoff,
                        const float* __restrict__ bias, int dolrelu) {
    int gw = (blockIdx.x * blockDim.x + threadIdx.x) >> 5;
    int lane = threadIdx.x & 31;
    if (gw >= NNODES) return;
    float acc[CPL];
#pragma unroll
    for (int c = 0; c < CPL; c++) acc[c] = 0.f;
    int e0 = g_rowptr[gw], e1 = g_rowptr[gw + 1];
    for (int e = e0; e < e1; e++) {
        const float* xr = X + (size_t)g_esrc[e] * ldx + xoff;
#pragma unroll
        for (int c = 0; c < CPL; c++) acc[c] += xr[lane + 32 * c];
    }
    float* orow = O + (size_t)gw * ldo + ooff;
#pragma unroll
    for (int c = 0; c < CPL; c++) {
        float v = acc[c];
        if (addY) v += addY[(size_t)gw * ldy + yoff + lane + 32 * c];
        if (bias) v += bias[lane + 32 * c];
        if (dolrelu) v = lrelu(v);
        orow[lane + 32 * c] = v;
    }
}

// ---------------- weight concatenation helpers ----------------
__global__ void assemble_rows(const float* __restrict__ top, const float* __restrict__ bot,
                              float* __restrict__ W, int rowsTop, int rowsBot, int ncols) {
    int i = blockIdx.x * blockDim.x + threadIdx.x;
    int total = (rowsTop + rowsBot) * ncols;
    if (i < total) {
        int r = i / ncols, c = i % ncols;
        W[i] = (r < rowsTop) ? top[r * ncols + c] : bot[(r - rowsTop) * ncols + c];
    }
}

__global__ void assemble_cols(const float* __restrict__ left, const float* __restrict__ right,
                              float* __restrict__ W, int nrows, int colsL, int colsR) {
    int i = blockIdx.x * blockDim.x + threadIdx.x;
    int nc = colsL + colsR;
    int total = nrows * nc;
    if (i < total) {
        int r = i / nc, c = i % nc;
        W[i] = (c < colsL) ? left[r * colsL + c] : right[r * colsR + (c - colsL)];
    }
}

// ---------------- SGEMM: C[M,N] = A[M,K] @ B[K,N] (+bias)(lrelu) ----------------
// 128x128 tile, BK=8, 256 threads, 8x8 per thread, packed f32x2 FMA.
#define BM 128
#define BN 128
#define BK 8

template <bool BIAS, bool LRELU>
__global__ __launch_bounds__(256, 2)
void sgemm_kernel(const float* __restrict__ A, const float* __restrict__ B,
                  const float* __restrict__ bias, float* __restrict__ C,
                  int M, int N, int K) {
    __shared__ __align__(16) float As[BK][BM];
    __shared__ __align__(16) float Bs[BK][BN];
    int tid = threadIdx.x;
    int bm = blockIdx.y * BM;
    int bn = blockIdx.x * BN;

    int arow = tid >> 1;            // 0..127
    int acol = (tid & 1) * 4;       // 0 or 4
    int brow = tid >> 5;            // 0..7
    int bcol = (tid & 31) * 4;      // 0..124
    int ty = (tid >> 4) * 8;        // 0..120 (row offset)
    int tx = (tid & 15) * 8;        // 0..120 (col offset)

    unsigned long long acc[8][4];   // [i][col pair], each = packed f32x2
#pragma unroll
    for (int i = 0; i < 8; i++)
#pragma unroll
        for (int jp = 0; jp < 4; jp++) acc[i][jp] = 0ull;

    for (int k0 = 0; k0 < K; k0 += BK) {
        int gr = bm + arow;
        float4 av = make_float4(0.f, 0.f, 0.f, 0.f);
        if (gr < M) av = *reinterpret_cast<const float4*>(A + (size_t)gr * K + k0 + acol);
        As[acol + 0][arow] = av.x;
        As[acol + 1][arow] = av.y;
        As[acol + 2][arow] = av.z;
        As[acol + 3][arow] = av.w;
        float4 bv = *reinterpret_cast<const float4*>(B + (size_t)(k0 + brow) * N + bn + bcol);
        *reinterpret_cast<float4*>(&Bs[brow][bcol]) = bv;
        __syncthreads();
#pragma unroll
        for (int k = 0; k < BK; k++) {
            unsigned long long bq[4];
#pragma unroll
            for (int jp = 0; jp < 4; jp++)
                bq[jp] = *reinterpret_cast<const unsigned long long*>(&Bs[k][tx + 2 * jp]);
            float4 a0 = *reinterpret_cast<const float4*>(&As[k][ty]);
            float4 a1 = *reinterpret_cast<const float4*>(&As[k][ty + 4]);
            float areg[8] = {a0.x, a0.y, a0.z, a0.w, a1.x, a1.y, a1.z, a1.w};
#pragma unroll
            for (int i = 0; i < 8; i++) {
                unsigned int au = __float_as_uint(areg[i]);
                unsigned long long a2;
                asm("mov.b64 %0, {%1, %1};" : "=l"(a2) : "r"(au));
#pragma unroll
                for (int jp = 0; jp < 4; jp++)
                    asm("fma.rn.f32x2 %0, %1, %2, %0;" : "+l"(acc[i][jp]) : "l"(a2), "l"(bq[jp]));
            }
        }
        __syncthreads();
    }

    float bvec[8];
#pragma unroll
    for (int j = 0; j < 8; j++) bvec[j] = BIAS ? bias[bn + tx + j] : 0.f;

#pragma unroll
    for (int i = 0; i < 8; i++) {
        int gr = bm + ty + i;
        if (gr >= M) continue;
        float o[8];
#pragma unroll
        for (int jp = 0; jp < 4; jp++) {
            float2 p = *reinterpret_cast<float2*>(&acc[i][jp]);
            o[2 * jp + 0] = p.x;
            o[2 * jp + 1] = p.y;
        }
#pragma unroll
        for (int j = 0; j < 8; j++) {
            float v = o[j] + bvec[j];
            if (LRELU) v = lrelu(v);
            o[j] = v;
        }
        float* cp = C + (size_t)gr * N + bn + tx;
        *reinterpret_cast<float4*>(cp) = make_float4(o[0], o[1], o[2], o[3]);
        *reinterpret_cast<float4*>(cp + 4) = make_float4(o[4], o[5], o[6], o[7]);
    }
}

// ---------------- pooling + logits ----------------
__global__ void count_kernel(const int* __restrict__ batch) {
    int n = blockIdx.x * blockDim.x + threadIdx.x;
    if (n < NNODES) atomicAdd(&g_counts[batch[n]], 1.0f);
}

__global__ void pool_kernel(const int* __restrict__ batch) {
    long long total = (long long)NNODES * 256;
    for (long long i = blockIdx.x * (long long)blockDim.x + threadIdx.x; i < total;
         i += (long long)gridDim.x * blockDim.x) {
        int n = (int)(i >> 8);
        int c = (int)(i & 255);
        atomicAdd(&g_pooled[batch[n] * 256 + c], g_lat[(size_t)n * 512 + c]);
    }
}

__global__ void logits_kernel(const float* __restrict__ w_lin, const float* __restrict__ b_lin,
                              float* __restrict__ out) {
    int g = blockIdx.x;
    int warp = threadIdx.x >> 5;
    int lane = threadIdx.x & 31;
    if (warp >= 7) return;
    float s = 0.f;
#pragma unroll
    for (int k = 0; k < 8; k++) {
        int c = lane + 32 * k;
        s += g_pooled[g * 256 + c] * w_lin[c * 7 + warp];
    }
#pragma unroll
    for (int off = 16; off; off >>= 1) s += __shfl_xor_sync(0xffffffffu, s, off);
    if (lane == 0) {
        float cnt = g_counts[g];
        if (cnt < 1.f) cnt = 1.f;
        out[g * 7 + warp] = s / cnt + b_lin[warp];
    }
}

// ---------------- launcher ----------------
extern "C" void kernel_launch(void* const* d_in, const int* in_sizes, int n_in,
                              void* d_out, int out_size) {
    const int*   x       = (const int*)d_in[0];
    const int*   ei      = (const int*)d_in[1];
    const int*   batch   = (const int*)d_in[2];
    const float* emb     = (const float*)d_in[3];
    const float* w1_rel  = (const float*)d_in[4];
    const float* w1_root = (const float*)d_in[5];
    const float* b1      = (const float*)d_in[6];
    const float* w2_rel  = (const float*)d_in[7];
    const float* w2_root = (const float*)d_in[8];
    const float* b2      = (const float*)d_in[9];
    const float* we_rel  = (const float*)d_in[10];
    const float* we_root = (const float*)d_in[11];
    const float* be      = (const float*)d_in[12];
    const float* wd_rel  = (const float*)d_in[13];
    const float* wd_root = (const float*)d_in[14];
    const float* bd      = (const float*)d_in[15];
    const float* w_lin   = (const float*)d_in[16];
    const float* b_lin   = (const float*)d_in[17];

    float* out    = (float*)d_out;
    float* logits = out;
    float* recon  = out + (size_t)NGRAPHS * 7;
    float* orig   = recon + (size_t)NNODES * 1024;

    const int E = NEDGES;

    void *pdeg, *pfill, *ppooled, *pcounts, *pbuf1, *pY, *plat, *pW2, *pWe, *pWd;
    cudaGetSymbolAddress(&pdeg, g_deg);
    cudaGetSymbolAddress(&pfill, g_fill);
    cudaGetSymbolAddress(&ppooled, g_pooled);
    cudaGetSymbolAddress(&pcounts, g_counts);
    cudaGetSymbolAddress(&pbuf1, g_buf1);
    cudaGetSymbolAddress(&pY, g_Y);
    cudaGetSymbolAddress(&plat, g_lat);
    cudaGetSymbolAddress(&pW2, g_W2);
    cudaGetSymbolAddress(&pWe, g_We);
    cudaGetSymbolAddress(&pWd, g_Wd);
    float* buf1 = (float*)pbuf1;
    float* Y    = (float*)pY;
    float* lat  = (float*)plat;
    float* W2   = (float*)pW2;
    float* We   = (float*)pWe;
    float* Wd   = (float*)pWd;

    cudaMemsetAsync(pdeg, 0, NNODES * sizeof(int));
    cudaMemsetAsync(pfill, 0, NNODES * sizeof(int));
    cudaMemsetAsync(ppooled, 0, NGRAPHS * 256 * sizeof(float));
    cudaMemsetAsync(pcounts, 0, NGRAPHS * sizeof(float));

    // CSR build (edges grouped by dst)
    deg_kernel<<<(E + 255) / 256, 256>>>(ei + E, E);
    scan_kernel<<<1, 1024>>>();
    fill_kernel<<<(E + 255) / 256, 256>>>(ei, ei + E, E);

    // embedding + conv1
    embed_kernel<<<(NNODES + 255) / 256, 256>>>(x, emb);
    int warpBlocks = (NNODES * 32 + 255) / 256;
    conv1_kernel<<<warpBlocks, 256>>>(w1_rel, w1_root, b1);

    // conv2: aggr(h1) then [h1|aggr] @ [w2_root; w2_rel] + b2, lrelu -> original
    agg_csr<2><<<warpBlocks, 256>>>(buf1, 128, 0, buf1, 128, 64, nullptr, 0, 0, nullptr, 0);
    assemble_rows<<<(128 * 1024 + 255) / 256, 256>>>(w2_root, w2_rel, W2, 64, 64, 1024);
    {
        dim3 grid(1024 / BN, (NNODES + BM - 1) / BM);
        sgemm_kernel<true, true><<<grid, 256>>>(buf1, W2, b2, orig, NNODES, 1024, 128);
    }

    // enc: Y = orig @ [we_root | we_rel]; latent = lrelu(aggr(Y_rel) + Y_root + be)
    assemble_cols<<<(1024 * 512 + 255) / 256, 256>>>(we_root, we_rel, We, 1024, 256, 256);
    {
        dim3 grid(512 / BN, (NNODES + BM - 1) / BM);
        sgemm_kernel<false, false><<<grid, 256>>>(orig, We, nullptr, Y, NNODES, 512, 1024);
    }
    agg_csr<8><<<warpBlocks, 256>>>(Y, 512, 256, lat, 512, 0, Y, 512, 0, be, 1);

    // global mean pool + logits
    count_kernel<<<(NNODES + 255) / 256, 256>>>(batch);
    pool_kernel<<<2048, 256>>>(batch);
    logits_kernel<<<NGRAPHS, 256>>>(w_lin, b_lin, logits);

    // dec: aggr(latent) then [latent|aggr] @ [wd_root; wd_rel] + bd, lrelu -> reconstructed
    agg_csr<8><<<warpBlocks, 256>>>(lat, 512, 0, lat, 512, 256, nullptr, 0, 0, nullptr, 0);
    assemble_rows<<<(512 * 1024 + 255) / 256, 256>>>(wd_root, wd_rel, Wd, 256, 256, 1024);
    {
        dim3 grid(1024 / BN, (NNODES + BM - 1) / BM);
        sgemm_kernel<true, true><<<grid, 256>>>(lat, Wd, bd, recon, NNODES, 1024, 512);
    }
}

// round 6
// speedup vs baseline: 1.5489x; 1.5489x over previous
#include <cuda_runtime.h>
#include <cuda_bf16.h>
#include <cstdint>

#define NNODES  50000
#define NEDGES  800000
#define NGRAPHS 256
#define SLOPE   0.01f

// ---------------- device scratch (no allocations allowed) ----------------
__device__ int   g_deg[NNODES];
__device__ int   g_fill[NNODES];
__device__ int   g_rowptr[NNODES + 1];
__device__ int   g_esrc[NEDGES];
__device__ float g_h0[NNODES * 3];
__device__ __align__(16) float g_buf1[(size_t)NNODES * 128];   // cols 0-63: h1, 64-127: aggr(h1)
__device__ __align__(16) float g_Y[(size_t)NNODES * 512];      // cols 0-255: Y_root, 256-511: Y_rel
__device__ __align__(16) float g_lat[(size_t)NNODES * 512];    // cols 0-255: latent, 256-511: aggr(latent)
__device__ __align__(16) __nv_bfloat16 g_Ah1[(size_t)NNODES * 128];   // buf1 split
__device__ __align__(16) __nv_bfloat16 g_Al1[(size_t)NNODES * 128];
__device__ __align__(16) __nv_bfloat16 g_Ahi[(size_t)NNODES * 1024];  // orig split / lat split (reused)
__device__ __align__(16) __nv_bfloat16 g_Alo[(size_t)NNODES * 1024];
__device__ __align__(16) __nv_bfloat16 g_Bhi[1024 * 1024];
__device__ __align__(16) __nv_bfloat16 g_Blo[1024 * 1024];
__device__ float g_pooled[NGRAPHS * 256];
__device__ float g_counts[NGRAPHS];

__device__ __forceinline__ float lrelu(float v) { return v >= 0.f ? v : SLOPE * v; }

// ---------------- CSR build ----------------
__global__ void deg_kernel(const int* __restrict__ dst, int E) {
    int i = blockIdx.x * blockDim.x + threadIdx.x;
    if (i < E) atomicAdd(&g_deg[dst[i]], 1);
}

__global__ void scan_kernel() {
    __shared__ int sm[1024];
    const int CH = (NNODES + 1023) / 1024;
    int t = threadIdx.x;
    int base = t * CH;
    int s = 0;
    for (int i = 0; i < CH; i++) {
        int idx = base + i;
        if (idx < NNODES) s += g_deg[idx];
    }
    sm[t] = s;
    __syncthreads();
    for (int off = 1; off < 1024; off <<= 1) {
        int v = (t >= off) ? sm[t - off] : 0;
        __syncthreads();
        sm[t] += v;
        __syncthreads();
    }
    int prefix = (t > 0) ? sm[t - 1] : 0;
    for (int i = 0; i < CH; i++) {
        int idx = base + i;
        if (idx < NNODES) {
            g_rowptr[idx] = prefix;
            prefix += g_deg[idx];
        }
    }
    if (t == 0) g_rowptr[NNODES] = sm[1023];
}

__global__ void fill_kernel(const int* __restrict__ src, const int* __restrict__ dst, int E) {
    int i = blockIdx.x * blockDim.x + threadIdx.x;
    if (i < E) {
        int d = dst[i];
        int pos = atomicAdd(&g_fill[d], 1);
        g_esrc[g_rowptr[d] + pos] = src[i];
    }
}

// ---------------- embedding + conv1 (3 -> 64, fused) ----------------
__global__ void embed_kernel(const int* __restrict__ x, const float* __restrict__ emb) {
    int n = blockIdx.x * blockDim.x + threadIdx.x;
    if (n < NNODES) {
        int l = x[n];
        g_h0[n * 3 + 0] = emb[l * 3 + 0];
        g_h0[n * 3 + 1] = emb[l * 3 + 1];
        g_h0[n * 3 + 2] = emb[l * 3 + 2];
    }
}

__global__ void conv1_kernel(const float* __restrict__ w_rel, const float* __restrict__ w_root,
                             const float* __restrict__ b) {
    int gw = (blockIdx.x * blockDim.x + threadIdx.x) >> 5;
    int lane = threadIdx.x & 31;
    if (gw >= NNODES) return;
    float s0 = 0.f, s1 = 0.f, s2 = 0.f;
    int e0 = g_rowptr[gw], e1 = g_rowptr[gw + 1];
    for (int e = e0 + lane; e < e1; e += 32) {
        const float* h = &g_h0[3 * g_esrc[e]];
        s0 += h[0]; s1 += h[1]; s2 += h[2];
    }
#pragma unroll
    for (int off = 16; off; off >>= 1) {
        s0 += __shfl_xor_sync(0xffffffffu, s0, off);
        s1 += __shfl_xor_sync(0xffffffffu, s1, off);
        s2 += __shfl_xor_sync(0xffffffffu, s2, off);
    }
    float r0 = g_h0[gw * 3 + 0], r1 = g_h0[gw * 3 + 1], r2 = g_h0[gw * 3 + 2];
#pragma unroll
    for (int q = 0; q < 2; q++) {
        int j = lane + 32 * q;
        float v = b[j] + r0 * w_root[j] + r1 * w_root[64 + j] + r2 * w_root[128 + j]
                       + s0 * w_rel[j]  + s1 * w_rel[64 + j]  + s2 * w_rel[128 + j];
        g_buf1[(size_t)gw * 128 + j] = lrelu(v);
    }
}

// ---------------- generic warp-per-node CSR aggregation ----------------
template <int CPL>
__global__ void agg_csr(const float* __restrict__ X, int ldx, int xoff,
                        float* __restrict__ O, int ldo, int ooff,
                        const float* __restrict__ addY, int ldy, int yoff,
                        const float* __restrict__ bias, int dolrelu) {
    int gw = (blockIdx.x * blockDim.x + threadIdx.x) >> 5;
    int lane = threadIdx.x & 31;
    if (gw >= NNODES) return;
    float acc[CPL];
#pragma unroll
    for (int c = 0; c < CPL; c++) acc[c] = 0.f;
    int e0 = g_rowptr[gw], e1 = g_rowptr[gw + 1];
    for (int e = e0; e < e1; e++) {
        const float* xr = X + (size_t)g_esrc[e] * ldx + xoff;
#pragma unroll
        for (int c = 0; c < CPL; c++) acc[c] += xr[lane + 32 * c];
    }
    float* orow = O + (size_t)gw * ldo + ooff;
#pragma unroll
    for (int c = 0; c < CPL; c++) {
        float v = acc[c];
        if (addY) v += addY[(size_t)gw * ldy + yoff + lane + 32 * c];
        if (bias) v += bias[lane + 32 * c];
        if (dolrelu) v = lrelu(v);
        orow[lane + 32 * c] = v;
    }
}

// ---------------- fp32 -> hi/lo bf16 split (vectorized x4) ----------------
__global__ void fsplit_kernel(const float* __restrict__ X, __nv_bfloat16* __restrict__ Hi,
                              __nv_bfloat16* __restrict__ Lo, int n4) {
    int i = blockIdx.x * blockDim.x + threadIdx.x;
    if (i >= n4) return;
    float4 v = reinterpret_cast<const float4*>(X)[i];
    __nv_bfloat16 h0 = __float2bfloat16(v.x), h1 = __float2bfloat16(v.y);
    __nv_bfloat16 h2 = __float2bfloat16(v.z), h3 = __float2bfloat16(v.w);
    __nv_bfloat16 l0 = __float2bfloat16(v.x - __bfloat162float(h0));
    __nv_bfloat16 l1 = __float2bfloat16(v.y - __bfloat162float(h1));
    __nv_bfloat16 l2 = __float2bfloat16(v.z - __bfloat162float(h2));
    __nv_bfloat16 l3 = __float2bfloat16(v.w - __bfloat162float(h3));
    reinterpret_cast<__nv_bfloat162*>(Hi)[2 * i + 0] = __halves2bfloat162(h0, h1);
    reinterpret_cast<__nv_bfloat162*>(Hi)[2 * i + 1] = __halves2bfloat162(h2, h3);
    reinterpret_cast<__nv_bfloat162*>(Lo)[2 * i + 0] = __halves2bfloat162(l0, l1);
    reinterpret_cast<__nv_bfloat162*>(Lo)[2 * i + 1] = __halves2bfloat162(l2, l3);
}

// ---------------- weight concat + transpose + split -> Bt[n*K+k] hi/lo ----------------
// mode 0 (rows concat): B[k][n] = k<split ? P[k*N+n] : Q[(k-split)*N+n]
// mode 1 (cols concat): B[k][n] = n<split ? P[k*split+n] : Q[k*(N-split)+(n-split)]
__global__ void wsplit_kernel(const float* __restrict__ P, const float* __restrict__ Q,
                              __nv_bfloat16* __restrict__ Hi, __nv_bfloat16* __restrict__ Lo,
                              int K, int N, int split, int mode) {
    int i = blockIdx.x * blockDim.x + threadIdx.x;
    if (i >= N * K) return;
    int n = i / K, k = i % K;
    float v;
    if (mode == 0) v = (k < split) ? P[(size_t)k * N + n] : Q[(size_t)(k - split) * N + n];
    else           v = (n < split) ? P[(size_t)k * split + n] : Q[(size_t)k * (N - split) + (n - split)];
    __nv_bfloat16 h = __float2bfloat16(v);
    Hi[i] = h;
    Lo[i] = __float2bfloat16(v - __bfloat162float(h));
}

// ---------------- tensor-core GEMM via mma.sync (3x bf16 split) ----------------
// C[M,N] = A[M,K] @ B[K,N], B given as Bt[N,K] (k contiguous).
// CTA tile 128x128, BK=32, 8 warps, warp tile 32(M) x 64(N).
#define TS_A 40   // padded smem row stride (bf16 units): conflict-free for ldmatrix

__device__ __forceinline__ uint32_t smem_u32(const void* p) {
    uint32_t a;
    asm("{ .reg .u64 t; cvta.to.shared.u64 t, %1; cvt.u32.u64 %0, t; }" : "=r"(a) : "l"(p));
    return a;
}
__device__ __forceinline__ void ldsm4(uint32_t& r0, uint32_t& r1, uint32_t& r2, uint32_t& r3,
                                      uint32_t addr) {
    asm volatile("ldmatrix.sync.aligned.m8n8.x4.shared.b16 {%0,%1,%2,%3}, [%4];"
                 : "=r"(r0), "=r"(r1), "=r"(r2), "=r"(r3) : "r"(addr));
}
__device__ __forceinline__ void mma16816(float* c, uint32_t a0, uint32_t a1, uint32_t a2,
                                         uint32_t a3, uint32_t b0, uint32_t b1) {
    asm volatile(
        "mma.sync.aligned.m16n8k16.row.col.f32.bf16.bf16.f32 "
        "{%0,%1,%2,%3}, {%4,%5,%6,%7}, {%8,%9}, {%0,%1,%2,%3};"
        : "+f"(c[0]), "+f"(c[1]), "+f"(c[2]), "+f"(c[3])
        : "r"(a0), "r"(a1), "r"(a2), "r"(a3), "r"(b0), "r"(b1));
}

template <bool BIASRELU, bool SPLITOUT>
__global__ __launch_bounds__(256)
void gemm_mma(const __nv_bfloat16* __restrict__ Ahi, const __nv_bfloat16* __restrict__ Alo,
              const __nv_bfloat16* __restrict__ Bhi, const __nv_bfloat16* __restrict__ Blo,
              const float* __restrict__ bias, float* __restrict__ C,
              __nv_bfloat16* __restrict__ Chi, __nv_bfloat16* __restrict__ Clo,
              int M, int N, int K) {
    __shared__ __align__(16) __nv_bfloat16 sAh[128 * TS_A];
    __shared__ __align__(16) __nv_bfloat16 sAl[128 * TS_A];
    __shared__ __align__(16) __nv_bfloat16 sBh[128 * TS_A];
    __shared__ __align__(16) __nv_bfloat16 sBl[128 * TS_A];

    const int tid = threadIdx.x, wid = tid >> 5, lane = tid & 31;
    const int bm = blockIdx.y * 128, bn = blockIdx.x * 128;
    const int wm = (wid & 3) * 32;   // warp M offset within CTA tile
    const int wn = (wid >> 2) * 64;  // warp N offset within CTA tile

    float acc[2][8][4];
#pragma unroll
    for (int mi = 0; mi < 2; mi++)
#pragma unroll
        for (int nj = 0; nj < 8; nj++)
#pragma unroll
            for (int q = 0; q < 4; q++) acc[mi][nj][q] = 0.f;

    // ldmatrix source addresses (computed once)
    const uint32_t aBaseH = smem_u32(sAh), aBaseL = smem_u32(sAl);
    const uint32_t bBaseH = smem_u32(sBh), bBaseL = smem_u32(sBl);
    const int aRow = wm + (lane & 15);
    const int aColSel = (lane >> 4) * 8;           // 0 or 8
    const int bMat = lane >> 3, bR = lane & 7;     // B x4: matrix id, row in matrix
    const int bRowOff = (bMat >> 1) * 8 + bR;      // n offset within 16-wide group
    const int bColSel = (bMat & 1) * 8;            // k offset 0/8 within k16

    for (int k0 = 0; k0 < K; k0 += 32) {
        // load 4 tiles of [128 rows x 32 cols] bf16, vectorized 16B
#pragma unroll
        for (int it = 0; it < 8; it++) {
            int idx = tid + it * 256;      // 0..2047
            int t = idx >> 9;              // which tile 0..3
            int r = (idx >> 2) & 127;      // row
            int c = (idx & 3) * 8;         // col (bf16 units)
            uint4 v;
            if (t < 2) {
                int gr = bm + r;
                if (gr < M)
                    v = *reinterpret_cast<const uint4*>((t == 0 ? Ahi : Alo) + (size_t)gr * K + k0 + c);
                else
                    v = make_uint4(0, 0, 0, 0);
                *reinterpret_cast<uint4*>((t == 0 ? sAh : sAl) + r * TS_A + c) = v;
            } else {
                int gn = bn + r;   // N is a multiple of 128
                v = *reinterpret_cast<const uint4*>((t == 2 ? Bhi : Blo) + (size_t)gn * K + k0 + c);
                *reinterpret_cast<uint4*>((t == 2 ? sBh : sBl) + r * TS_A + c) = v;
            }
        }
        __syncthreads();

#pragma unroll
        for (int ks = 0; ks < 2; ks++) {
            const int kk = ks * 16;
            // A fragments (hi & lo) for 2 m16 tiles
            uint32_t ah[2][4], al[2][4];
#pragma unroll
            for (int mi = 0; mi < 2; mi++) {
                uint32_t off = ((aRow + mi * 16) * TS_A + kk + aColSel) * 2;
                ldsm4(ah[mi][0], ah[mi][1], ah[mi][2], ah[mi][3], aBaseH + off);
                ldsm4(al[mi][0], al[mi][1], al[mi][2], al[mi][3], aBaseL + off);
            }
            // B: 4 groups of n16 (covers 64 n)
#pragma unroll
            for (int nb = 0; nb < 4; nb++) {
                uint32_t off = ((wn + nb * 16 + bRowOff) * TS_A + kk + bColSel) * 2;
                uint32_t bh0, bh1, bh2, bh3, bl0, bl1, bl2, bl3;
                ldsm4(bh0, bh1, bh2, bh3, bBaseH + off);
                ldsm4(bl0, bl1, bl2, bl3, bBaseL + off);
#pragma unroll
                for (int mi = 0; mi < 2; mi++) {
                    mma16816(acc[mi][2 * nb + 0], ah[mi][0], ah[mi][1], ah[mi][2], ah[mi][3], bh0, bh1);
                    mma16816(acc[mi][2 * nb + 1], ah[mi][0], ah[mi][1], ah[mi][2], ah[mi][3], bh2, bh3);
                    mma16816(acc[mi][2 * nb + 0], ah[mi][0], ah[mi][1], ah[mi][2], ah[mi][3], bl0, bl1);
                    mma16816(acc[mi][2 * nb + 1], ah[mi][0], ah[mi][1], ah[mi][2], ah[mi][3], bl2, bl3);
                    mma16816(acc[mi][2 * nb + 0], al[mi][0], al[mi][1], al[mi][2], al[mi][3], bh0, bh1);
                    mma16816(acc[mi][2 * nb + 1], al[mi][0], al[mi][1], al[mi][2], al[mi][3], bh2, bh3);
                }
            }
        }
        __syncthreads();
    }

    // epilogue: acc[mi][nj] rows = bm+wm+mi*16 + (lane>>2) (+8), cols = bn+wn+nj*8 + 2*(lane&3)
    const int crow = lane >> 2;
    const int ccol = 2 * (lane & 3);
#pragma unroll
    for (int mi = 0; mi < 2; mi++) {
#pragma unroll
        for (int half = 0; half < 2; half++) {
            int gr = bm + wm + mi * 16 + crow + half * 8;
            if (gr >= M) continue;
#pragma unroll
            for (int nj = 0; nj < 8; nj++) {
                int gc = bn + wn + nj * 8 + ccol;
                float v0 = acc[mi][nj][2 * half + 0];
                float v1 = acc[mi][nj][2 * half + 1];
                if (BIASRELU) {
                    v0 = lrelu(v0 + bias[gc]);
                    v1 = lrelu(v1 + bias[gc + 1]);
                }
                *reinterpret_cast<float2*>(C + (size_t)gr * N + gc) = make_float2(v0, v1);
                if (SPLITOUT) {
                    __nv_bfloat16 h0 = __float2bfloat16(v0), h1 = __float2bfloat16(v1);
                    __nv_bfloat16 q0 = __float2bfloat16(v0 - __bfloat162float(h0));
                    __nv_bfloat16 q1 = __float2bfloat16(v1 - __bfloat162float(h1));
                    size_t oi = (size_t)gr * N + gc;
                    *reinterpret_cast<__nv_bfloat162*>(Chi + oi) = __halves2bfloat162(h0, h1);
                    *reinterpret_cast<__nv_bfloat162*>(Clo + oi) = __halves2bfloat162(q0, q1);
                }
            }
        }
    }
}

// ---------------- pooling + logits ----------------
__global__ void count_kernel(const int* __restrict__ batch) {
    int n = blockIdx.x * blockDim.x + threadIdx.x;
    if (n < NNODES) atomicAdd(&g_counts[batch[n]], 1.0f);
}

__global__ void pool_kernel(const int* __restrict__ batch) {
    long long total = (long long)NNODES * 256;
    for (long long i = blockIdx.x * (long long)blockDim.x + threadIdx.x; i < total;
         i += (long long)gridDim.x * blockDim.x) {
        int n = (int)(i >> 8);
        int c = (int)(i & 255);
        atomicAdd(&g_pooled[batch[n] * 256 + c], g_lat[(size_t)n * 512 + c]);
    }
}

__global__ void logits_kernel(const float* __restrict__ w_lin, const float* __restrict__ b_lin,
                              float* __restrict__ out) {
    int g = blockIdx.x;
    int warp = threadIdx.x >> 5;
    int lane = threadIdx.x & 31;
    if (warp >= 7) return;
    float s = 0.f;
#pragma unroll
    for (int k = 0; k < 8; k++) {
        int c = lane + 32 * k;
        s += g_pooled[g * 256 + c] * w_lin[c * 7 + warp];
    }
#pragma unroll
    for (int off = 16; off; off >>= 1) s += __shfl_xor_sync(0xffffffffu, s, off);
    if (lane == 0) {
        float cnt = g_counts[g];
        if (cnt < 1.f) cnt = 1.f;
        out[g * 7 + warp] = s / cnt + b_lin[warp];
    }
}

// ---------------- launcher ----------------
extern "C" void kernel_launch(void* const* d_in, const int* in_sizes, int n_in,
                              void* d_out, int out_size) {
    const int*   x       = (const int*)d_in[0];
    const int*   ei      = (const int*)d_in[1];
    const int*   batch   = (const int*)d_in[2];
    const float* emb     = (const float*)d_in[3];
    const float* w1_rel  = (const float*)d_in[4];
    const float* w1_root = (const float*)d_in[5];
    const float* b1      = (const float*)d_in[6];
    const float* w2_rel  = (const float*)d_in[7];
    const float* w2_root = (const float*)d_in[8];
    const float* b2      = (const float*)d_in[9];
    const float* we_rel  = (const float*)d_in[10];
    const float* we_root = (const float*)d_in[11];
    const float* be      = (const float*)d_in[12];
    const float* wd_rel  = (const float*)d_in[13];
    const float* wd_root = (const float*)d_in[14];
    const float* bd      = (const float*)d_in[15];
    const float* w_lin   = (const float*)d_in[16];
    const float* b_lin   = (const float*)d_in[17];

    float* out    = (float*)d_out;
    float* logits = out;
    float* recon  = out + (size_t)NGRAPHS * 7;
    float* orig   = recon + (size_t)NNODES * 1024;

    const int E = NEDGES;

    void *pdeg, *pfill, *ppooled, *pcounts, *pbuf1, *pY, *plat;
    void *pAh1, *pAl1, *pAhi, *pAlo, *pBhi, *pBlo;
    cudaGetSymbolAddress(&pdeg, g_deg);
    cudaGetSymbolAddress(&pfill, g_fill);
    cudaGetSymbolAddress(&ppooled, g_pooled);
    cudaGetSymbolAddress(&pcounts, g_counts);
    cudaGetSymbolAddress(&pbuf1, g_buf1);
    cudaGetSymbolAddress(&pY, g_Y);
    cudaGetSymbolAddress(&plat, g_lat);
    cudaGetSymbolAddress(&pAh1, g_Ah1);
    cudaGetSymbolAddress(&pAl1, g_Al1);
    cudaGetSymbolAddress(&pAhi, g_Ahi);
    cudaGetSymbolAddress(&pAlo, g_Alo);
    cudaGetSymbolAddress(&pBhi, g_Bhi);
    cudaGetSymbolAddress(&pBlo, g_Blo);
    float* buf1 = (float*)pbuf1;
    float* Y    = (float*)pY;
    float* lat  = (float*)plat;
    __nv_bfloat16* Ah1 = (__nv_bfloat16*)pAh1;
    __nv_bfloat16* Al1 = (__nv_bfloat16*)pAl1;
    __nv_bfloat16* Ahi = (__nv_bfloat16*)pAhi;
    __nv_bfloat16* Alo = (__nv_bfloat16*)pAlo;
    __nv_bfloat16* Bhi = (__nv_bfloat16*)pBhi;
    __nv_bfloat16* Blo = (__nv_bfloat16*)pBlo;

    cudaMemsetAsync(pdeg, 0, NNODES * sizeof(int));
    cudaMemsetAsync(pfill, 0, NNODES * sizeof(int));
    cudaMemsetAsync(ppooled, 0, NGRAPHS * 256 * sizeof(float));
    cudaMemsetAsync(pcounts, 0, NGRAPHS * sizeof(float));

    // CSR build (edges grouped by dst)
    deg_kernel<<<(E + 255) / 256, 256>>>(ei + E, E);
    scan_kernel<<<1, 1024>>>();
    fill_kernel<<<(E + 255) / 256, 256>>>(ei, ei + E, E);

    // embedding + conv1
    embed_kernel<<<(NNODES + 255) / 256, 256>>>(x, emb);
    int warpBlocks = (NNODES * 32 + 255) / 256;
    conv1_kernel<<<warpBlocks, 256>>>(w1_rel, w1_root, b1);

    // conv2: aggr(h1), split A, split B, tensor GEMM -> original (+fused split of orig)
    agg_csr<2><<<warpBlocks, 256>>>(buf1, 128, 0, buf1, 128, 64, nullptr, 0, 0, nullptr, 0);
    {
        int n4 = NNODES * 128 / 4;
        fsplit_kernel<<<(n4 + 255) / 256, 256>>>(buf1, Ah1, Al1, n4);
    }
    wsplit_kernel<<<(1024 * 128 + 255) / 256, 256>>>(w2_root, w2_rel, Bhi, Blo, 128, 1024, 64, 0);
    {
        dim3 grid(1024 / 128, (NNODES + 127) / 128);
        gemm_mma<true, true><<<grid, 256>>>(Ah1, Al1, Bhi, Blo, b2, orig,
                                            Ahi, Alo, NNODES, 1024, 128);
    }

    // enc: Y = orig @ [we_root | we_rel]; latent = lrelu(aggr(Y_rel) + Y_root + be)
    wsplit_kernel<<<(512 * 1024 + 255) / 256, 256>>>(we_root, we_rel, Bhi, Blo, 1024, 512, 256, 1);
    {
        dim3 grid(512 / 128, (NNODES + 127) / 128);
        gemm_mma<false, false><<<grid, 256>>>(Ahi, Alo, Bhi, Blo, nullptr, Y,
                                              nullptr, nullptr, NNODES, 512, 1024);
    }
    agg_csr<8><<<warpBlocks, 256>>>(Y, 512, 256, lat, 512, 0, Y, 512, 0, be, 1);

    // global mean pool + logits
    count_kernel<<<(NNODES + 255) / 256, 256>>>(batch);
    pool_kernel<<<2048, 256>>>(batch);
    logits_kernel<<<NGRAPHS, 256>>>(w_lin, b_lin, logits);

    // dec: aggr(latent); split lat; tensor GEMM -> reconstructed
    agg_csr<8><<<warpBlocks, 256>>>(lat, 512, 0, lat, 512, 256, nullptr, 0, 0, nullptr, 0);
    {
        int n4 = NNODES * 512 / 4;
        fsplit_kernel<<<(n4 + 255) / 256, 256>>>(lat, Ahi, Alo, n4);
    }
    wsplit_kernel<<<(1024 * 512 + 255) / 256, 256>>>(wd_root, wd_rel, Bhi, Blo, 512, 1024, 256, 0);
    {
        dim3 grid(1024 / 128, (NNODES + 127) / 128);
        gemm_mma<true, false><<<grid, 256>>>(Ahi, Alo, Bhi, Blo, bd, recon,
                                             nullptr, nullptr, NNODES, 1024, 512);
    }
}

// round 11
// speedup vs baseline: 1.9331x; 1.2480x over previous
#include <cuda_runtime.h>
#include <cuda_bf16.h>
#include <cstdint>

#define NNODES  50000
#define NEDGES  800000
#define NGRAPHS 256
#define SLOPE   0.01f

// ---------------- device scratch (no allocations allowed) ----------------
__device__ int   g_deg[NNODES];
__device__ int   g_fill[NNODES];
__device__ int   g_rowptr[NNODES + 1];
__device__ int   g_esrc[NEDGES];
__device__ float g_h0[NNODES * 3];
__device__ __align__(16) float g_buf1[(size_t)NNODES * 64];    // h1 (fp32, agg source)
__device__ __align__(16) float g_Y[(size_t)NNODES * 512];      // cols 0-255: Y_root, 256-511: Y_rel
__device__ __align__(16) float g_lat[(size_t)NNODES * 256];    // latent (pool + agg source)
__device__ __align__(16) __nv_bfloat16 g_Ah1[(size_t)NNODES * 128];   // [h1 | aggr(h1)] split hi
__device__ __align__(16) __nv_bfloat16 g_Al1[(size_t)NNODES * 128];
__device__ __align__(16) __nv_bfloat16 g_Ahi[(size_t)NNODES * 1024];  // orig split / [lat|aggr] split
__device__ __align__(16) __nv_bfloat16 g_Alo[(size_t)NNODES * 1024];
__device__ __align__(16) __nv_bfloat16 g_Bhi[1024 * 1024];
__device__ __align__(16) __nv_bfloat16 g_Blo[1024 * 1024];
__device__ float g_pooled[NGRAPHS * 256];
__device__ float g_counts[NGRAPHS];

__device__ __forceinline__ float lrelu(float v) { return v >= 0.f ? v : SLOPE * v; }

__device__ __forceinline__ void split2(float v0, float v1, __nv_bfloat16* Hi, __nv_bfloat16* Lo,
                                       size_t oi) {
    __nv_bfloat16 h0 = __float2bfloat16(v0), h1 = __float2bfloat16(v1);
    __nv_bfloat16 q0 = __float2bfloat16(v0 - __bfloat162float(h0));
    __nv_bfloat16 q1 = __float2bfloat16(v1 - __bfloat162float(h1));
    *reinterpret_cast<__nv_bfloat162*>(Hi + oi) = __halves2bfloat162(h0, h1);
    *reinterpret_cast<__nv_bfloat162*>(Lo + oi) = __halves2bfloat162(q0, q1);
}

// ---------------- CSR build ----------------
__global__ void deg_kernel(const int* __restrict__ dst, int E) {
    int i = blockIdx.x * blockDim.x + threadIdx.x;
    if (i < E) atomicAdd(&g_deg[dst[i]], 1);
}

__global__ void scan_kernel() {
    __shared__ int sm[1024];
    const int CH = (NNODES + 1023) / 1024;
    int t = threadIdx.x;
    int base = t * CH;
    int s = 0;
    for (int i = 0; i < CH; i++) {
        int idx = base + i;
        if (idx < NNODES) s += g_deg[idx];
    }
    sm[t] = s;
    __syncthreads();
    for (int off = 1; off < 1024; off <<= 1) {
        int v = (t >= off) ? sm[t - off] : 0;
        __syncthreads();
        sm[t] += v;
        __syncthreads();
    }
    int prefix = (t > 0) ? sm[t - 1] : 0;
    for (int i = 0; i < CH; i++) {
        int idx = base + i;
        if (idx < NNODES) {
            g_rowptr[idx] = prefix;
            prefix += g_deg[idx];
        }
    }
    if (t == 0) g_rowptr[NNODES] = sm[1023];
}

__global__ void fill_kernel(const int* __restrict__ src, const int* __restrict__ dst, int E) {
    int i = blockIdx.x * blockDim.x + threadIdx.x;
    if (i < E) {
        int d = dst[i];
        int pos = atomicAdd(&g_fill[d], 1);
        g_esrc[g_rowptr[d] + pos] = src[i];
    }
}

// ---------------- embedding + conv1 (3 -> 64, fused, split output) ----------------
__global__ void embed_kernel(const int* __restrict__ x, const float* __restrict__ emb) {
    int n = blockIdx.x * blockDim.x + threadIdx.x;
    if (n < NNODES) {
        int l = x[n];
        g_h0[n * 3 + 0] = emb[l * 3 + 0];
        g_h0[n * 3 + 1] = emb[l * 3 + 1];
        g_h0[n * 3 + 2] = emb[l * 3 + 2];
    }
}

__global__ void conv1_kernel(const float* __restrict__ w_rel, const float* __restrict__ w_root,
                             const float* __restrict__ b) {
    int gw = (blockIdx.x * blockDim.x + threadIdx.x) >> 5;
    int lane = threadIdx.x & 31;
    if (gw >= NNODES) return;
    float s0 = 0.f, s1 = 0.f, s2 = 0.f;
    int e0 = g_rowptr[gw], e1 = g_rowptr[gw + 1];
    for (int e = e0 + lane; e < e1; e += 32) {
        const float* h = &g_h0[3 * g_esrc[e]];
        s0 += h[0]; s1 += h[1]; s2 += h[2];
    }
#pragma unroll
    for (int off = 16; off; off >>= 1) {
        s0 += __shfl_xor_sync(0xffffffffu, s0, off);
        s1 += __shfl_xor_sync(0xffffffffu, s1, off);
        s2 += __shfl_xor_sync(0xffffffffu, s2, off);
    }
    float r0 = g_h0[gw * 3 + 0], r1 = g_h0[gw * 3 + 1], r2 = g_h0[gw * 3 + 2];
#pragma unroll
    for (int q = 0; q < 2; q++) {
        int j = lane + 32 * q;
        float t = b[j] + r0 * w_root[j] + r1 * w_root[64 + j] + r2 * w_root[128 + j]
                       + s0 * w_rel[j]  + s1 * w_rel[64 + j]  + s2 * w_rel[128 + j];
        float v = lrelu(t);
        g_buf1[(size_t)gw * 64 + j] = v;
        __nv_bfloat16 h = __float2bfloat16(v);
        g_Ah1[(size_t)gw * 128 + j] = h;
        g_Al1[(size_t)gw * 128 + j] = __float2bfloat16(v - __bfloat162float(h));
    }
}

// ---------------- warp-per-node CSR aggregation, optional fp32 + split outputs ----------------
template <int CPL>
__global__ void agg_csr(const float* __restrict__ X, int ldx, int xoff,
                        float* __restrict__ O, int ldo, int ooff,
                        const float* __restrict__ addY, int ldy, int yoff,
                        const float* __restrict__ bias, int dolrelu,
                        __nv_bfloat16* __restrict__ Ohi, __nv_bfloat16* __restrict__ Olo,
                        int lds, int soff) {
    int gw = (blockIdx.x * blockDim.x + threadIdx.x) >> 5;
    int lane = threadIdx.x & 31;
    if (gw >= NNODES) return;
    float acc[CPL];
#pragma unroll
    for (int c = 0; c < CPL; c++) acc[c] = 0.f;
    int e0 = g_rowptr[gw], e1 = g_rowptr[gw + 1];
    int e = e0;
    for (; e + 1 < e1; e += 2) {
        const float* xr0 = X + (size_t)g_esrc[e] * ldx + xoff;
        const float* xr1 = X + (size_t)g_esrc[e + 1] * ldx + xoff;
#pragma unroll
        for (int c = 0; c < CPL; c++) acc[c] += xr0[lane + 32 * c] + xr1[lane + 32 * c];
    }
    if (e < e1) {
        const float* xr = X + (size_t)g_esrc[e] * ldx + xoff;
#pragma unroll
        for (int c = 0; c < CPL; c++) acc[c] += xr[lane + 32 * c];
    }
#pragma unroll
    for (int c = 0; c < CPL; c++) {
        float v = acc[c];
        if (addY) v += addY[(size_t)gw * ldy + yoff + lane + 32 * c];
        if (bias) v += bias[lane + 32 * c];
        if (dolrelu) v = lrelu(v);
        acc[c] = v;
        if (O) O[(size_t)gw * ldo + ooff + lane + 32 * c] = v;
    }
    if (Ohi) {
#pragma unroll
        for (int c = 0; c < CPL; c++) {
            size_t oi = (size_t)gw * lds + soff + lane + 32 * c;
            __nv_bfloat16 h = __float2bfloat16(acc[c]);
            Ohi[oi] = h;
            Olo[oi] = __float2bfloat16(acc[c] - __bfloat162float(h));
        }
    }
}

// ---------------- weight concat + transpose + split -> Bt[n*K+k] hi/lo ----------------
// mode 0 (rows concat): B[k][n] = k<split ? P[k*N+n] : Q[(k-split)*N+n]
// mode 1 (cols concat): B[k][n] = n<split ? P[k*split+n] : Q[k*(N-split)+(n-split)]
__global__ void wsplit_kernel(const float* __restrict__ P, const float* __restrict__ Q,
                              __nv_bfloat16* __restrict__ Hi, __nv_bfloat16* __restrict__ Lo,
                              int K, int N, int split, int mode) {
    int i = blockIdx.x * blockDim.x + threadIdx.x;
    if (i >= N * K) return;
    int n = i / K, k = i % K;
    float v;
    if (mode == 0) v = (k < split) ? P[(size_t)k * N + n] : Q[(size_t)(k - split) * N + n];
    else           v = (n < split) ? P[(size_t)k * split + n] : Q[(size_t)k * (N - split) + (n - split)];
    __nv_bfloat16 h = __float2bfloat16(v);
    Hi[i] = h;
    Lo[i] = __float2bfloat16(v - __bfloat162float(h));
}

// ---------------- tensor-core GEMM via mma.sync, cp.async double-buffered ----------------
// C[M,N] = A[M,K] @ B[K,N], B given as Bt[N,K]. CTA 128x128, BK=32, 8 warps (32x64 each).
#define TS_A 40                          // padded smem row stride (bf16), conflict-free
#define TILE_B (128 * TS_A * 2)          // 10240 bytes per tile
#define STAGE_B (4 * TILE_B)             // 40960 bytes per stage
#define GEMM_SMEM (2 * STAGE_B)          // 81920 bytes

__device__ __forceinline__ uint32_t smem_u32(const void* p) {
    uint32_t a;
    asm("{ .reg .u64 t; cvta.to.shared.u64 t, %1; cvt.u32.u64 %0, t; }" : "=r"(a) : "l"(p));
    return a;
}
__device__ __forceinline__ void cpasync16(uint32_t dst, const void* src, int src_bytes) {
    asm volatile("cp.async.cg.shared.global [%0], [%1], 16, %2;"
                 :: "r"(dst), "l"(src), "r"(src_bytes) : "memory");
}
__device__ __forceinline__ void cp_commit() {
    asm volatile("cp.async.commit_group;" ::: "memory");
}
template <int NLEFT>
__device__ __forceinline__ void cp_wait() {
    asm volatile("cp.async.wait_group %0;" :: "n"(NLEFT) : "memory");
}
__device__ __forceinline__ void ldsm4(uint32_t& r0, uint32_t& r1, uint32_t& r2, uint32_t& r3,
                                      uint32_t addr) {
    asm volatile("ldmatrix.sync.aligned.m8n8.x4.shared.b16 {%0,%1,%2,%3}, [%4];"
                 : "=r"(r0), "=r"(r1), "=r"(r2), "=r"(r3) : "r"(addr));
}
__device__ __forceinline__ void mma16816(float* c, uint32_t a0, uint32_t a1, uint32_t a2,
                                         uint32_t a3, uint32_t b0, uint32_t b1) {
    asm volatile(
        "mma.sync.aligned.m16n8k16.row.col.f32.bf16.bf16.f32 "
        "{%0,%1,%2,%3}, {%4,%5,%6,%7}, {%8,%9}, {%0,%1,%2,%3};"
        : "+f"(c[0]), "+f"(c[1]), "+f"(c[2]), "+f"(c[3])
        : "r"(a0), "r"(a1), "r"(a2), "r"(a3), "r"(b0), "r"(b1));
}

__device__ __forceinline__ void gemm_prefetch(
    uint32_t stage_base, const __nv_bfloat16* Ahi, const __nv_bfloat16* Alo,
    const __nv_bfloat16* Bhi, const __nv_bfloat16* Blo,
    int bm, int bn, int M, int K, int k0, int tid) {
#pragma unroll
    for (int it = 0; it < 8; it++) {
        int idx = tid + it * 256;      // 0..2047
        int t = idx >> 9;              // tile 0..3
        int r = (idx >> 2) & 127;      // row
        int c = (idx & 3) * 8;         // col (bf16 units)
        uint32_t dst = stage_base + t * TILE_B + (r * TS_A + c) * 2;
        if (t < 2) {
            int gr = bm + r;
            int ok = (gr < M) ? 16 : 0;
            int grc = (gr < M) ? gr : (M - 1);
            const __nv_bfloat16* src = (t == 0 ? Ahi : Alo) + (size_t)grc * K + k0 + c;
            cpasync16(dst, src, ok);
        } else {
            int gn = bn + r;   // N multiple of 128
            const __nv_bfloat16* src = (t == 2 ? Bhi : Blo) + (size_t)gn * K + k0 + c;
            cpasync16(dst, src, 16);
        }
    }
}

template <bool BIASRELU, bool SPLITOUT>
__global__ __launch_bounds__(256)
void gemm_mma(const __nv_bfloat16* __restrict__ Ahi, const __nv_bfloat16* __restrict__ Alo,
              const __nv_bfloat16* __restrict__ Bhi, const __nv_bfloat16* __restrict__ Blo,
              const float* __restrict__ bias, float* __restrict__ C,
              __nv_bfloat16* __restrict__ Chi, __nv_bfloat16* __restrict__ Clo,
              int M, int N, int K) {
    extern __shared__ __align__(16) char dynsm[];
    const uint32_t sbase = smem_u32(dynsm);

    const int tid = threadIdx.x, wid = tid >> 5, lane = tid & 31;
    const int bm = blockIdx.y * 128, bn = blockIdx.x * 128;
    const int wm = (wid & 3) * 32;
    const int wn = (wid >> 2) * 64;

    float acc[2][8][4];
#pragma unroll
    for (int mi = 0; mi < 2; mi++)
#pragma unroll
        for (int nj = 0; nj < 8; nj++)
#pragma unroll
            for (int q = 0; q < 4; q++) acc[mi][nj][q] = 0.f;

    const int aRow = wm + (lane & 15);
    const int aColSel = (lane >> 4) * 8;
    const int bMat = lane >> 3, bR = lane & 7;
    const int bRowOff = (bMat >> 1) * 8 + bR;
    const int bColSel = (bMat & 1) * 8;

    const int nch = K / 32;
    gemm_prefetch(sbase, Ahi, Alo, Bhi, Blo, bm, bn, M, K, 0, tid);
    cp_commit();

    for (int ch = 0; ch < nch; ch++) {
        if (ch + 1 < nch) {
            gemm_prefetch(sbase + ((ch + 1) & 1) * STAGE_B, Ahi, Alo, Bhi, Blo,
                          bm, bn, M, K, (ch + 1) * 32, tid);
            cp_commit();
            cp_wait<1>();
        } else {
            cp_wait<0>();
        }
        __syncthreads();

        const uint32_t st = sbase + (ch & 1) * STAGE_B;
        const uint32_t aBaseH = st, aBaseL = st + TILE_B;
        const uint32_t bBaseH = st + 2 * TILE_B, bBaseL = st + 3 * TILE_B;

#pragma unroll
        for (int ks = 0; ks < 2; ks++) {
            const int kk = ks * 16;
            uint32_t ah[2][4], al[2][4];
#pragma unroll
            for (int mi = 0; mi < 2; mi++) {
                uint32_t off = ((aRow + mi * 16) * TS_A + kk + aColSel) * 2;
                ldsm4(ah[mi][0], ah[mi][1], ah[mi][2], ah[mi][3], aBaseH + off);
                ldsm4(al[mi][0], al[mi][1], al[mi][2], al[mi][3], aBaseL + off);
            }
#pragma unroll
            for (int nb = 0; nb < 4; nb++) {
                uint32_t off = ((wn + nb * 16 + bRowOff) * TS_A + kk + bColSel) * 2;
                uint32_t bh0, bh1, bh2, bh3, bl0, bl1, bl2, bl3;
                ldsm4(bh0, bh1, bh2, bh3, bBaseH + off);
                ldsm4(bl0, bl1, bl2, bl3, bBaseL + off);
#pragma unroll
                for (int mi = 0; mi < 2; mi++) {
                    mma16816(acc[mi][2 * nb + 0], ah[mi][0], ah[mi][1], ah[mi][2], ah[mi][3], bh0, bh1);
                    mma16816(acc[mi][2 * nb + 1], ah[mi][0], ah[mi][1], ah[mi][2], ah[mi][3], bh2, bh3);
                    mma16816(acc[mi][2 * nb + 0], ah[mi][0], ah[mi][1], ah[mi][2], ah[mi][3], bl0, bl1);
                    mma16816(acc[mi][2 * nb + 1], ah[mi][0], ah[mi][1], ah[mi][2], ah[mi][3], bl2, bl3);
                    mma16816(acc[mi][2 * nb + 0], al[mi][0], al[mi][1], al[mi][2], al[mi][3], bh0, bh1);
                    mma16816(acc[mi][2 * nb + 1], al[mi][0], al[mi][1], al[mi][2], al[mi][3], bh2, bh3);
                }
            }
        }
        __syncthreads();
    }

    const int crow = lane >> 2;
    const int ccol = 2 * (lane & 3);
#pragma unroll
    for (int mi = 0; mi < 2; mi++) {
#pragma unroll
        for (int half = 0; half < 2; half++) {
            int gr = bm + wm + mi * 16 + crow + half * 8;
            if (gr >= M) continue;
#pragma unroll
            for (int nj = 0; nj < 8; nj++) {
                int gc = bn + wn + nj * 8 + ccol;
                float v0 = acc[mi][nj][2 * half + 0];
                float v1 = acc[mi][nj][2 * half + 1];
                if (BIASRELU) {
                    v0 = lrelu(v0 + bias[gc]);
                    v1 = lrelu(v1 + bias[gc + 1]);
                }
                *reinterpret_cast<float2*>(C + (size_t)gr * N + gc) = make_float2(v0, v1);
                if (SPLITOUT) split2(v0, v1, Chi, Clo, (size_t)gr * N + gc);
            }
        }
    }
}

// ---------------- pooling + logits ----------------
__global__ void count_kernel(const int* __restrict__ batch) {
    int n = blockIdx.x * blockDim.x + threadIdx.x;
    if (n < NNODES) atomicAdd(&g_counts[batch[n]], 1.0f);
}

__global__ void pool_kernel(const int* __restrict__ batch) {
    long long total = (long long)NNODES * 256;
    for (long long i = blockIdx.x * (long long)blockDim.x + threadIdx.x; i < total;
         i += (long long)gridDim.x * blockDim.x) {
        int n = (int)(i >> 8);
        int c = (int)(i & 255);
        atomicAdd(&g_pooled[batch[n] * 256 + c], g_lat[(size_t)n * 256 + c]);
    }
}

__global__ void logits_kernel(const float* __restrict__ w_lin, const float* __restrict__ b_lin,
                              float* __restrict__ out) {
    int g = blockIdx.x;
    int warp = threadIdx.x >> 5;
    int lane = threadIdx.x & 31;
    if (warp >= 7) return;
    float s = 0.f;
#pragma unroll
    for (int k = 0; k < 8; k++) {
        int c = lane + 32 * k;
        s += g_pooled[g * 256 + c] * w_lin[c * 7 + warp];
    }
#pragma unroll
    for (int off = 16; off; off >>= 1) s += __shfl_xor_sync(0xffffffffu, s, off);
    if (lane == 0) {
        float cnt = g_counts[g];
        if (cnt < 1.f) cnt = 1.f;
        out[g * 7 + warp] = s / cnt + b_lin[warp];
    }
}

// ---------------- launcher ----------------
extern "C" void kernel_launch(void* const* d_in, const int* in_sizes, int n_in,
                              void* d_out, int out_size) {
    const int*   x       = (const int*)d_in[0];
    const int*   ei      = (const int*)d_in[1];
    const int*   batch   = (const int*)d_in[2];
    const float* emb     = (const float*)d_in[3];
    const float* w1_rel  = (const float*)d_in[4];
    const float* w1_root = (const float*)d_in[5];
    const float* b1      = (const float*)d_in[6];
    const float* w2_rel  = (const float*)d_in[7];
    const float* w2_root = (const float*)d_in[8];
    const float* b2      = (const float*)d_in[9];
    const float* we_rel  = (const float*)d_in[10];
    const float* we_root = (const float*)d_in[11];
    const float* be      = (const float*)d_in[12];
    const float* wd_rel  = (const float*)d_in[13];
    const float* wd_root = (const float*)d_in[14];
    const float* bd      = (const float*)d_in[15];
    const float* w_lin   = (const float*)d_in[16];
    const float* b_lin   = (const float*)d_in[17];

    float* out    = (float*)d_out;
    float* logits = out;
    float* recon  = out + (size_t)NGRAPHS * 7;
    float* orig   = recon + (size_t)NNODES * 1024;

    const int E = NEDGES;

    void *pdeg, *pfill, *ppooled, *pcounts, *pbuf1, *pY, *plat;
    void *pAh1, *pAl1, *pAhi, *pAlo, *pBhi, *pBlo;
    cudaGetSymbolAddress(&pdeg, g_deg);
    cudaGetSymbolAddress(&pfill, g_fill);
    cudaGetSymbolAddress(&ppooled, g_pooled);
    cudaGetSymbolAddress(&pcounts, g_counts);
    cudaGetSymbolAddress(&pbuf1, g_buf1);
    cudaGetSymbolAddress(&pY, g_Y);
    cudaGetSymbolAddress(&plat, g_lat);
    cudaGetSymbolAddress(&pAh1, g_Ah1);
    cudaGetSymbolAddress(&pAl1, g_Al1);
    cudaGetSymbolAddress(&pAhi, g_Ahi);
    cudaGetSymbolAddress(&pAlo, g_Alo);
    cudaGetSymbolAddress(&pBhi, g_Bhi);
    cudaGetSymbolAddress(&pBlo, g_Blo);
    float* buf1 = (float*)pbuf1;
    float* Y    = (float*)pY;
    float* lat  = (float*)plat;
    __nv_bfloat16* Ah1 = (__nv_bfloat16*)pAh1;
    __nv_bfloat16* Al1 = (__nv_bfloat16*)pAl1;
    __nv_bfloat16* Ahi = (__nv_bfloat16*)pAhi;
    __nv_bfloat16* Alo = (__nv_bfloat16*)pAlo;
    __nv_bfloat16* Bhi = (__nv_bfloat16*)pBhi;
    __nv_bfloat16* Blo = (__nv_bfloat16*)pBlo;

    cudaFuncSetAttribute(gemm_mma<true, true>,   cudaFuncAttributeMaxDynamicSharedMemorySize, GEMM_SMEM);
    cudaFuncSetAttribute(gemm_mma<false, false>, cudaFuncAttributeMaxDynamicSharedMemorySize, GEMM_SMEM);
    cudaFuncSetAttribute(gemm_mma<true, false>,  cudaFuncAttributeMaxDynamicSharedMemorySize, GEMM_SMEM);

    cudaMemsetAsync(pdeg, 0, NNODES * sizeof(int));
    cudaMemsetAsync(pfill, 0, NNODES * sizeof(int));
    cudaMemsetAsync(ppooled, 0, NGRAPHS * 256 * sizeof(float));
    cudaMemsetAsync(pcounts, 0, NGRAPHS * sizeof(float));

    // CSR build (edges grouped by dst)
    deg_kernel<<<(E + 255) / 256, 256>>>(ei + E, E);
    scan_kernel<<<1, 1024>>>();
    fill_kernel<<<(E + 255) / 256, 256>>>(ei, ei + E, E);

    // embedding + conv1 (writes fp32 h1 + its bf16 split into Ah1/Al1 cols 0-63)
    embed_kernel<<<(NNODES + 255) / 256, 256>>>(x, emb);
    int warpBlocks = (NNODES * 32 + 255) / 256;
    conv1_kernel<<<warpBlocks, 256>>>(w1_rel, w1_root, b1);

    // conv2: aggr(h1) -> split only into Ah1/Al1 cols 64-127; weights; GEMM -> orig (+split)
    agg_csr<2><<<warpBlocks, 256>>>(buf1, 64, 0, nullptr, 0, 0, nullptr, 0, 0,
                                    nullptr, 0, Ah1, Al1, 128, 64);
    wsplit_kernel<<<(1024 * 128 + 255) / 256, 256>>>(w2_root, w2_rel, Bhi, Blo, 128, 1024, 64, 0);
    {
        dim3 grid(1024 / 128, (NNODES + 127) / 128);
        gemm_mma<true, true><<<grid, 256, GEMM_SMEM>>>(Ah1, Al1, Bhi, Blo, b2, orig,
                                                       Ahi, Alo, NNODES, 1024, 128);
    }

    // enc: Y = orig @ [we_root | we_rel];
    // latent = lrelu(aggr(Y_rel) + Y_root + be) -> lat fp32 (stride 256) + split (stride 512, cols 0-255)
    wsplit_kernel<<<(512 * 1024 + 255) / 256, 256>>>(we_root, we_rel, Bhi, Blo, 1024, 512, 256, 1);
    {
        dim3 grid(512 / 128, (NNODES + 127) / 128);
        gemm_mma<false, false><<<grid, 256, GEMM_SMEM>>>(Ahi, Alo, Bhi, Blo, nullptr, Y,
                                                         nullptr, nullptr, NNODES, 512, 1024);
    }
    agg_csr<8><<<warpBlocks, 256>>>(Y, 512, 256, lat, 256, 0, Y, 512, 0, be, 1,
                                    Ahi, Alo, 512, 0);

    // global mean pool + logits
    count_kernel<<<(NNODES + 255) / 256, 256>>>(batch);
    pool_kernel<<<2048, 256>>>(batch);
    logits_kernel<<<NGRAPHS, 256>>>(w_lin, b_lin, logits);

    // dec-prep: aggr(latent) -> split only into Ahi/Alo cols 256-511
    agg_csr<8><<<warpBlocks, 256>>>(lat, 256, 0, nullptr, 0, 0, nullptr, 0, 0,
                                    nullptr, 0, Ahi, Alo, 512, 256);

    // dec: GEMM -> reconstructed
    wsplit_kernel<<<(1024 * 512 + 255) / 256, 256>>>(wd_root, wd_rel, Bhi, Blo, 512, 1024, 256, 0);
    {
        dim3 grid(1024 / 128, (NNODES + 127) / 128);
        gemm_mma<true, false><<<grid, 256, GEMM_SMEM>>>(Ahi, Alo, Bhi, Blo, bd, recon,
                                                        nullptr, nullptr, NNODES, 1024, 512);
    }
}

// round 12
// speedup vs baseline: 2.2966x; 1.1881x over previous
#include <cuda_runtime.h>
#include <cuda_bf16.h>
#include <cstdint>

#define NNODES  50000
#define NEDGES  800000
#define NGRAPHS 256
#define SLOPE   0.01f

// ---------------- device scratch (no allocations allowed) ----------------
__device__ int   g_deg[NNODES];
__device__ int   g_fill[NNODES];
__device__ int   g_rowptr[NNODES + 1];
__device__ int   g_esrc[NEDGES];
__device__ int   g_gstart[NGRAPHS + 1];
__device__ float g_h0[NNODES * 3];
__device__ __align__(16) float g_buf1[(size_t)NNODES * 64];    // h1 (fp32, agg source)
__device__ __align__(16) float g_Y[(size_t)NNODES * 512];      // cols 0-255: Y_root, 256-511: Y_rel
__device__ __align__(16) float g_lat[(size_t)NNODES * 256];    // latent (pool + agg source)
__device__ __align__(16) __nv_bfloat16 g_Ah1[(size_t)NNODES * 128];   // [h1 | aggr(h1)] split hi
__device__ __align__(16) __nv_bfloat16 g_Al1[(size_t)NNODES * 128];
__device__ __align__(16) __nv_bfloat16 g_Ahi[(size_t)NNODES * 1024];  // orig split / [lat|aggr] split
__device__ __align__(16) __nv_bfloat16 g_Alo[(size_t)NNODES * 1024];
__device__ __align__(16) __nv_bfloat16 g_Bhi[1024 * 1024];
__device__ __align__(16) __nv_bfloat16 g_Blo[1024 * 1024];

__device__ __forceinline__ float lrelu(float v) { return v >= 0.f ? v : SLOPE * v; }

__device__ __forceinline__ void split2(float v0, float v1, __nv_bfloat16* Hi, __nv_bfloat16* Lo,
                                       size_t oi) {
    __nv_bfloat16 h0 = __float2bfloat16(v0), h1 = __float2bfloat16(v1);
    __nv_bfloat16 q0 = __float2bfloat16(v0 - __bfloat162float(h0));
    __nv_bfloat16 q1 = __float2bfloat16(v1 - __bfloat162float(h1));
    *reinterpret_cast<__nv_bfloat162*>(Hi + oi) = __halves2bfloat162(h0, h1);
    *reinterpret_cast<__nv_bfloat162*>(Lo + oi) = __halves2bfloat162(q0, q1);
}

__device__ __forceinline__ void split4(float4 v, __nv_bfloat16* Hi, __nv_bfloat16* Lo, size_t oi) {
    __nv_bfloat162 h01 = __halves2bfloat162(__float2bfloat16(v.x), __float2bfloat16(v.y));
    __nv_bfloat162 h23 = __halves2bfloat162(__float2bfloat16(v.z), __float2bfloat16(v.w));
    float2 hx = make_float2(__bfloat162float(__low2bfloat16(h01)), __bfloat162float(__high2bfloat16(h01)));
    float2 hy = make_float2(__bfloat162float(__low2bfloat16(h23)), __bfloat162float(__high2bfloat16(h23)));
    __nv_bfloat162 l01 = __halves2bfloat162(__float2bfloat16(v.x - hx.x), __float2bfloat16(v.y - hx.y));
    __nv_bfloat162 l23 = __halves2bfloat162(__float2bfloat16(v.z - hy.x), __float2bfloat16(v.w - hy.y));
    uint2 uh, ul;
    uh.x = *reinterpret_cast<uint32_t*>(&h01); uh.y = *reinterpret_cast<uint32_t*>(&h23);
    ul.x = *reinterpret_cast<uint32_t*>(&l01); ul.y = *reinterpret_cast<uint32_t*>(&l23);
    *reinterpret_cast<uint2*>(Hi + oi) = uh;
    *reinterpret_cast<uint2*>(Lo + oi) = ul;
}

// ---------------- CSR build ----------------
__global__ void deg_kernel(const int* __restrict__ dst, int E) {
    int i = blockIdx.x * blockDim.x + threadIdx.x;
    if (i < E) atomicAdd(&g_deg[dst[i]], 1);
}

__global__ void scan_kernel() {
    __shared__ int sm[1024];
    const int CH = (NNODES + 1023) / 1024;
    int t = threadIdx.x;
    int base = t * CH;
    int s = 0;
    for (int i = 0; i < CH; i++) {
        int idx = base + i;
        if (idx < NNODES) s += g_deg[idx];
    }
    sm[t] = s;
    __syncthreads();
    for (int off = 1; off < 1024; off <<= 1) {
        int v = (t >= off) ? sm[t - off] : 0;
        __syncthreads();
        sm[t] += v;
        __syncthreads();
    }
    int prefix = (t > 0) ? sm[t - 1] : 0;
    for (int i = 0; i < CH; i++) {
        int idx = base + i;
        if (idx < NNODES) {
            g_rowptr[idx] = prefix;
            prefix += g_deg[idx];
        }
    }
    if (t == 0) g_rowptr[NNODES] = sm[1023];
}

__global__ void fill_kernel(const int* __restrict__ src, const int* __restrict__ dst, int E) {
    int i = blockIdx.x * blockDim.x + threadIdx.x;
    if (i < E) {
        int d = dst[i];
        int pos = atomicAdd(&g_fill[d], 1);
        g_esrc[g_rowptr[d] + pos] = src[i];
    }
}

// ---------------- graph segment boundaries (batch is sorted) ----------------
__global__ void bounds_kernel(const int* __restrict__ batch) {
    int n = blockIdx.x * blockDim.x + threadIdx.x;
    if (n >= NNODES) return;
    int bn = batch[n];
    int bp = (n == 0) ? -1 : batch[n - 1];
    for (int g = bp + 1; g <= bn; g++) g_gstart[g] = n;
    if (n == NNODES - 1)
        for (int g = bn + 1; g <= NGRAPHS; g++) g_gstart[g] = NNODES;
}

// ---------------- embedding + conv1 (3 -> 64, fused, split output) ----------------
__global__ void embed_kernel(const int* __restrict__ x, const float* __restrict__ emb) {
    int n = blockIdx.x * blockDim.x + threadIdx.x;
    if (n < NNODES) {
        int l = x[n];
        g_h0[n * 3 + 0] = emb[l * 3 + 0];
        g_h0[n * 3 + 1] = emb[l * 3 + 1];
        g_h0[n * 3 + 2] = emb[l * 3 + 2];
    }
}

__global__ void conv1_kernel(const float* __restrict__ w_rel, const float* __restrict__ w_root,
                             const float* __restrict__ b) {
    int gw = (blockIdx.x * blockDim.x + threadIdx.x) >> 5;
    int lane = threadIdx.x & 31;
    if (gw >= NNODES) return;
    float s0 = 0.f, s1 = 0.f, s2 = 0.f;
    int e0 = g_rowptr[gw], e1 = g_rowptr[gw + 1];
    for (int e = e0 + lane; e < e1; e += 32) {
        const float* h = &g_h0[3 * g_esrc[e]];
        s0 += h[0]; s1 += h[1]; s2 += h[2];
    }
#pragma unroll
    for (int off = 16; off; off >>= 1) {
        s0 += __shfl_xor_sync(0xffffffffu, s0, off);
        s1 += __shfl_xor_sync(0xffffffffu, s1, off);
        s2 += __shfl_xor_sync(0xffffffffu, s2, off);
    }
    float r0 = g_h0[gw * 3 + 0], r1 = g_h0[gw * 3 + 1], r2 = g_h0[gw * 3 + 2];
#pragma unroll
    for (int q = 0; q < 2; q++) {
        int j = lane + 32 * q;
        float t = b[j] + r0 * w_root[j] + r1 * w_root[64 + j] + r2 * w_root[128 + j]
                       + s0 * w_rel[j]  + s1 * w_rel[64 + j]  + s2 * w_rel[128 + j];
        float v = lrelu(t);
        g_buf1[(size_t)gw * 64 + j] = v;
        __nv_bfloat16 h = __float2bfloat16(v);
        g_Ah1[(size_t)gw * 128 + j] = h;
        g_Al1[(size_t)gw * 128 + j] = __float2bfloat16(v - __bfloat162float(h));
    }
}

// ---------------- scalar warp-per-node CSR aggregation (64-col case) ----------------
template <int CPL>
__global__ void agg_csr(const float* __restrict__ X, int ldx, int xoff,
                        __nv_bfloat16* __restrict__ Ohi, __nv_bfloat16* __restrict__ Olo,
                        int lds, int soff) {
    int gw = (blockIdx.x * blockDim.x + threadIdx.x) >> 5;
    int lane = threadIdx.x & 31;
    if (gw >= NNODES) return;
    float acc[CPL];
#pragma unroll
    for (int c = 0; c < CPL; c++) acc[c] = 0.f;
    int e0 = g_rowptr[gw], e1 = g_rowptr[gw + 1];
    int e = e0;
    for (; e + 1 < e1; e += 2) {
        const float* xr0 = X + (size_t)g_esrc[e] * ldx + xoff;
        const float* xr1 = X + (size_t)g_esrc[e + 1] * ldx + xoff;
#pragma unroll
        for (int c = 0; c < CPL; c++) acc[c] += xr0[lane + 32 * c] + xr1[lane + 32 * c];
    }
    if (e < e1) {
        const float* xr = X + (size_t)g_esrc[e] * ldx + xoff;
#pragma unroll
        for (int c = 0; c < CPL; c++) acc[c] += xr[lane + 32 * c];
    }
#pragma unroll
    for (int c = 0; c < CPL; c++) {
        size_t oi = (size_t)gw * lds + soff + lane + 32 * c;
        __nv_bfloat16 h = __float2bfloat16(acc[c]);
        Ohi[oi] = h;
        Olo[oi] = __float2bfloat16(acc[c] - __bfloat162float(h));
    }
}

// ---------------- float4 warp-per-node CSR aggregation (256-col cases) ----------------
// lane handles cols [4*(lane+32c) .. +3] for c in [0,NC4)
template <int NC4>
__global__ void agg_csr4(const float* __restrict__ X, int ldx, int xoff,
                         float* __restrict__ O, int ldo, int ooff,
                         const float* __restrict__ addY, int ldy, int yoff,
                         const float* __restrict__ bias, int dolrelu,
                         __nv_bfloat16* __restrict__ Ohi, __nv_bfloat16* __restrict__ Olo,
                         int lds, int soff) {
    int gw = (blockIdx.x * blockDim.x + threadIdx.x) >> 5;
    int lane = threadIdx.x & 31;
    if (gw >= NNODES) return;
    float4 acc[NC4];
#pragma unroll
    for (int c = 0; c < NC4; c++) acc[c] = make_float4(0.f, 0.f, 0.f, 0.f);
    int e0 = g_rowptr[gw], e1 = g_rowptr[gw + 1];
    int e = e0;
    for (; e + 1 < e1; e += 2) {
        const float4* x0 = reinterpret_cast<const float4*>(X + (size_t)g_esrc[e] * ldx + xoff);
        const float4* x1 = reinterpret_cast<const float4*>(X + (size_t)g_esrc[e + 1] * ldx + xoff);
#pragma unroll
        for (int c = 0; c < NC4; c++) {
            float4 a = x0[lane + 32 * c];
            float4 b4 = x1[lane + 32 * c];
            acc[c].x += a.x + b4.x; acc[c].y += a.y + b4.y;
            acc[c].z += a.z + b4.z; acc[c].w += a.w + b4.w;
        }
    }
    if (e < e1) {
        const float4* xr = reinterpret_cast<const float4*>(X + (size_t)g_esrc[e] * ldx + xoff);
#pragma unroll
        for (int c = 0; c < NC4; c++) {
            float4 a = xr[lane + 32 * c];
            acc[c].x += a.x; acc[c].y += a.y; acc[c].z += a.z; acc[c].w += a.w;
        }
    }
#pragma unroll
    for (int c = 0; c < NC4; c++) {
        float4 v = acc[c];
        int colbase = 4 * (lane + 32 * c);
        if (addY) {
            float4 y = *reinterpret_cast<const float4*>(addY + (size_t)gw * ldy + yoff + colbase);
            v.x += y.x; v.y += y.y; v.z += y.z; v.w += y.w;
        }
        if (bias) {
            float4 bb = *reinterpret_cast<const float4*>(bias + colbase);
            v.x += bb.x; v.y += bb.y; v.z += bb.z; v.w += bb.w;
        }
        if (dolrelu) {
            v.x = lrelu(v.x); v.y = lrelu(v.y); v.z = lrelu(v.z); v.w = lrelu(v.w);
        }
        if (O) *reinterpret_cast<float4*>(O + (size_t)gw * ldo + ooff + colbase) = v;
        if (Ohi) split4(v, Ohi, Olo, (size_t)gw * lds + soff + colbase);
    }
}

// ---------------- weight concat + transpose + split -> Bt[n*K+k] hi/lo ----------------
__global__ void wsplit_kernel(const float* __restrict__ P, const float* __restrict__ Q,
                              __nv_bfloat16* __restrict__ Hi, __nv_bfloat16* __restrict__ Lo,
                              int K, int N, int split, int mode) {
    int i = blockIdx.x * blockDim.x + threadIdx.x;
    if (i >= N * K) return;
    int n = i / K, k = i % K;
    float v;
    if (mode == 0) v = (k < split) ? P[(size_t)k * N + n] : Q[(size_t)(k - split) * N + n];
    else           v = (n < split) ? P[(size_t)k * split + n] : Q[(size_t)k * (N - split) + (n - split)];
    __nv_bfloat16 h = __float2bfloat16(v);
    Hi[i] = h;
    Lo[i] = __float2bfloat16(v - __bfloat162float(h));
}

// ---------------- tensor-core GEMM via mma.sync, cp.async double-buffered ----------------
#define TS_A 40                          // padded smem row stride (bf16), conflict-free
#define TILE_B (128 * TS_A * 2)          // 10240 bytes per tile
#define STAGE_B (4 * TILE_B)             // 40960 bytes per stage
#define GEMM_SMEM (2 * STAGE_B)          // 81920 bytes

__device__ __forceinline__ uint32_t smem_u32(const void* p) {
    uint32_t a;
    asm("{ .reg .u64 t; cvta.to.shared.u64 t, %1; cvt.u32.u64 %0, t; }" : "=r"(a) : "l"(p));
    return a;
}
__device__ __forceinline__ void cpasync16(uint32_t dst, const void* src, int src_bytes) {
    asm volatile("cp.async.cg.shared.global [%0], [%1], 16, %2;"
                 :: "r"(dst), "l"(src), "r"(src_bytes) : "memory");
}
__device__ __forceinline__ void cp_commit() {
    asm volatile("cp.async.commit_group;" ::: "memory");
}
template <int NLEFT>
__device__ __forceinline__ void cp_wait() {
    asm volatile("cp.async.wait_group %0;" :: "n"(NLEFT) : "memory");
}
__device__ __forceinline__ void ldsm4(uint32_t& r0, uint32_t& r1, uint32_t& r2, uint32_t& r3,
                                      uint32_t addr) {
    asm volatile("ldmatrix.sync.aligned.m8n8.x4.shared.b16 {%0,%1,%2,%3}, [%4];"
                 : "=r"(r0), "=r"(r1), "=r"(r2), "=r"(r3) : "r"(addr));
}
__device__ __forceinline__ void mma16816(float* c, uint32_t a0, uint32_t a1, uint32_t a2,
                                         uint32_t a3, uint32_t b0, uint32_t b1) {
    asm volatile(
        "mma.sync.aligned.m16n8k16.row.col.f32.bf16.bf16.f32 "
        "{%0,%1,%2,%3}, {%4,%5,%6,%7}, {%8,%9}, {%0,%1,%2,%3};"
        : "+f"(c[0]), "+f"(c[1]), "+f"(c[2]), "+f"(c[3])
        : "r"(a0), "r"(a1), "r"(a2), "r"(a3), "r"(b0), "r"(b1));
}

__device__ __forceinline__ void gemm_prefetch(
    uint32_t stage_base, const __nv_bfloat16* Ahi, const __nv_bfloat16* Alo,
    const __nv_bfloat16* Bhi, const __nv_bfloat16* Blo,
    int bm, int bn, int M, int K, int k0, int tid) {
#pragma unroll
    for (int it = 0; it < 8; it++) {
        int idx = tid + it * 256;      // 0..2047
        int t = idx >> 9;              // tile 0..3
        int r = (idx >> 2) & 127;      // row
        int c = (idx & 3) * 8;         // col (bf16 units)
        uint32_t dst = stage_base + t * TILE_B + (r * TS_A + c) * 2;
        if (t < 2) {
            int gr = bm + r;
            int ok = (gr < M) ? 16 : 0;
            int grc = (gr < M) ? gr : (M - 1);
            const __nv_bfloat16* src = (t == 0 ? Ahi : Alo) + (size_t)grc * K + k0 + c;
            cpasync16(dst, src, ok);
        } else {
            int gn = bn + r;   // N multiple of 128
            const __nv_bfloat16* src = (t == 2 ? Bhi : Blo) + (size_t)gn * K + k0 + c;
            cpasync16(dst, src, 16);
        }
    }
}

template <bool BIASRELU, bool SPLITOUT>
__global__ __launch_bounds__(256, 2)
void gemm_mma(const __nv_bfloat16* __restrict__ Ahi, const __nv_bfloat16* __restrict__ Alo,
              const __nv_bfloat16* __restrict__ Bhi, const __nv_bfloat16* __restrict__ Blo,
              const float* __restrict__ bias, float* __restrict__ C,
              __nv_bfloat16* __restrict__ Chi, __nv_bfloat16* __restrict__ Clo,
              int M, int N, int K) {
    extern __shared__ __align__(16) char dynsm[];
    const uint32_t sbase = smem_u32(dynsm);

    const int tid = threadIdx.x, wid = tid >> 5, lane = tid & 31;
    const int bm = blockIdx.y * 128, bn = blockIdx.x * 128;
    const int wm = (wid & 3) * 32;
    const int wn = (wid >> 2) * 64;

    float acc[2][8][4];
#pragma unroll
    for (int mi = 0; mi < 2; mi++)
#pragma unroll
        for (int nj = 0; nj < 8; nj++)
#pragma unroll
            for (int q = 0; q < 4; q++) acc[mi][nj][q] = 0.f;

    const int aRow = wm + (lane & 15);
    const int aColSel = (lane >> 4) * 8;
    const int bMat = lane >> 3, bR = lane & 7;
    const int bRowOff = (bMat >> 1) * 8 + bR;
    const int bColSel = (bMat & 1) * 8;

    const int nch = K / 32;
    gemm_prefetch(sbase, Ahi, Alo, Bhi, Blo, bm, bn, M, K, 0, tid);
    cp_commit();

    for (int ch = 0; ch < nch; ch++) {
        if (ch + 1 < nch) {
            gemm_prefetch(sbase + ((ch + 1) & 1) * STAGE_B, Ahi, Alo, Bhi, Blo,
                          bm, bn, M, K, (ch + 1) * 32, tid);
            cp_commit();
            cp_wait<1>();
        } else {
            cp_wait<0>();
        }
        __syncthreads();

        const uint32_t st = sbase + (ch & 1) * STAGE_B;
        const uint32_t aBaseH = st, aBaseL = st + TILE_B;
        const uint32_t bBaseH = st + 2 * TILE_B, bBaseL = st + 3 * TILE_B;

#pragma unroll
        for (int ks = 0; ks < 2; ks++) {
            const int kk = ks * 16;
            uint32_t ah[2][4], al[2][4];
#pragma unroll
            for (int mi = 0; mi < 2; mi++) {
                uint32_t off = ((aRow + mi * 16) * TS_A + kk + aColSel) * 2;
                ldsm4(ah[mi][0], ah[mi][1], ah[mi][2], ah[mi][3], aBaseH + off);
                ldsm4(al[mi][0], al[mi][1], al[mi][2], al[mi][3], aBaseL + off);
            }
#pragma unroll
            for (int nb = 0; nb < 4; nb++) {
                uint32_t off = ((wn + nb * 16 + bRowOff) * TS_A + kk + bColSel) * 2;
                uint32_t bh0, bh1, bh2, bh3, bl0, bl1, bl2, bl3;
                ldsm4(bh0, bh1, bh2, bh3, bBaseH + off);
                ldsm4(bl0, bl1, bl2, bl3, bBaseL + off);
#pragma unroll
                for (int mi = 0; mi < 2; mi++) {
                    mma16816(acc[mi][2 * nb + 0], ah[mi][0], ah[mi][1], ah[mi][2], ah[mi][3], bh0, bh1);
                    mma16816(acc[mi][2 * nb + 1], ah[mi][0], ah[mi][1], ah[mi][2], ah[mi][3], bh2, bh3);
                    mma16816(acc[mi][2 * nb + 0], ah[mi][0], ah[mi][1], ah[mi][2], ah[mi][3], bl0, bl1);
                    mma16816(acc[mi][2 * nb + 1], ah[mi][0], ah[mi][1], ah[mi][2], ah[mi][3], bl2, bl3);
                    mma16816(acc[mi][2 * nb + 0], al[mi][0], al[mi][1], al[mi][2], al[mi][3], bh0, bh1);
                    mma16816(acc[mi][2 * nb + 1], al[mi][0], al[mi][1], al[mi][2], al[mi][3], bh2, bh3);
                }
            }
        }
        __syncthreads();
    }

    const int crow = lane >> 2;
    const int ccol = 2 * (lane & 3);
#pragma unroll
    for (int mi = 0; mi < 2; mi++) {
#pragma unroll
        for (int half = 0; half < 2; half++) {
            int gr = bm + wm + mi * 16 + crow + half * 8;
            if (gr >= M) continue;
#pragma unroll
            for (int nj = 0; nj < 8; nj++) {
                int gc = bn + wn + nj * 8 + ccol;
                float v0 = acc[mi][nj][2 * half + 0];
                float v1 = acc[mi][nj][2 * half + 1];
                if (BIASRELU) {
                    v0 = lrelu(v0 + bias[gc]);
                    v1 = lrelu(v1 + bias[gc + 1]);
                }
                *reinterpret_cast<float2*>(C + (size_t)gr * N + gc) = make_float2(v0, v1);
                if (SPLITOUT) split2(v0, v1, Chi, Clo, (size_t)gr * N + gc);
            }
        }
    }
}

// ---------------- fused mean-pool + logits (segmented over sorted batch) ----------------
__global__ void pool_logits_kernel(const float* __restrict__ w_lin,
                                   const float* __restrict__ b_lin, float* __restrict__ out) {
    __shared__ float sp[256];
    int g = blockIdx.x;
    int s = g_gstart[g], e2 = g_gstart[g + 1];
    int c = threadIdx.x;
    float sum = 0.f;
    for (int n = s; n < e2; n++) sum += g_lat[(size_t)n * 256 + c];
    float cnt = (float)(e2 - s);
    if (cnt < 1.f) cnt = 1.f;
    sp[c] = sum / cnt;
    __syncthreads();
    int warp = threadIdx.x >> 5, lane = threadIdx.x & 31;
    if (warp < 7) {
        float t = 0.f;
#pragma unroll
        for (int k = 0; k < 8; k++) {
            int cc = lane + 32 * k;
            t += sp[cc] * w_lin[cc * 7 + warp];
        }
#pragma unroll
        for (int off = 16; off; off >>= 1) t += __shfl_xor_sync(0xffffffffu, t, off);
        if (lane == 0) out[g * 7 + warp] = t + b_lin[warp];
    }
}

// ---------------- launcher ----------------
extern "C" void kernel_launch(void* const* d_in, const int* in_sizes, int n_in,
                              void* d_out, int out_size) {
    const int*   x       = (const int*)d_in[0];
    const int*   ei      = (const int*)d_in[1];
    const int*   batch   = (const int*)d_in[2];
    const float* emb     = (const float*)d_in[3];
    const float* w1_rel  = (const float*)d_in[4];
    const float* w1_root = (const float*)d_in[5];
    const float* b1      = (const float*)d_in[6];
    const float* w2_rel  = (const float*)d_in[7];
    const float* w2_root = (const float*)d_in[8];
    const float* b2      = (const float*)d_in[9];
    const float* we_rel  = (const float*)d_in[10];
    const float* we_root = (const float*)d_in[11];
    const float* be      = (const float*)d_in[12];
    const float* wd_rel  = (const float*)d_in[13];
    const float* wd_root = (const float*)d_in[14];
    const float* bd      = (const float*)d_in[15];
    const float* w_lin   = (const float*)d_in[16];
    const float* b_lin   = (const float*)d_in[17];

    float* out    = (float*)d_out;
    float* logits = out;
    float* recon  = out + (size_t)NGRAPHS * 7;
    float* orig   = recon + (size_t)NNODES * 1024;

    const int E = NEDGES;

    void *pdeg, *pfill, *pbuf1, *pY, *plat;
    void *pAh1, *pAl1, *pAhi, *pAlo, *pBhi, *pBlo;
    cudaGetSymbolAddress(&pdeg, g_deg);
    cudaGetSymbolAddress(&pfill, g_fill);
    cudaGetSymbolAddress(&pbuf1, g_buf1);
    cudaGetSymbolAddress(&pY, g_Y);
    cudaGetSymbolAddress(&plat, g_lat);
    cudaGetSymbolAddress(&pAh1, g_Ah1);
    cudaGetSymbolAddress(&pAl1, g_Al1);
    cudaGetSymbolAddress(&pAhi, g_Ahi);
    cudaGetSymbolAddress(&pAlo, g_Alo);
    cudaGetSymbolAddress(&pBhi, g_Bhi);
    cudaGetSymbolAddress(&pBlo, g_Blo);
    float* buf1 = (float*)pbuf1;
    float* Y    = (float*)pY;
    float* lat  = (float*)plat;
    __nv_bfloat16* Ah1 = (__nv_bfloat16*)pAh1;
    __nv_bfloat16* Al1 = (__nv_bfloat16*)pAl1;
    __nv_bfloat16* Ahi = (__nv_bfloat16*)pAhi;
    __nv_bfloat16* Alo = (__nv_bfloat16*)pAlo;
    __nv_bfloat16* Bhi = (__nv_bfloat16*)pBhi;
    __nv_bfloat16* Blo = (__nv_bfloat16*)pBlo;

    cudaFuncSetAttribute(gemm_mma<true, true>,   cudaFuncAttributeMaxDynamicSharedMemorySize, GEMM_SMEM);
    cudaFuncSetAttribute(gemm_mma<false, false>, cudaFuncAttributeMaxDynamicSharedMemorySize, GEMM_SMEM);
    cudaFuncSetAttribute(gemm_mma<true, false>,  cudaFuncAttributeMaxDynamicSharedMemorySize, GEMM_SMEM);

    cudaMemsetAsync(pdeg, 0, NNODES * sizeof(int));
    cudaMemsetAsync(pfill, 0, NNODES * sizeof(int));

    // CSR build (edges grouped by dst) + graph segment bounds
    deg_kernel<<<(E + 255) / 256, 256>>>(ei + E, E);
    scan_kernel<<<1, 1024>>>();
    fill_kernel<<<(E + 255) / 256, 256>>>(ei, ei + E, E);
    bounds_kernel<<<(NNODES + 255) / 256, 256>>>(batch);

    // embedding + conv1 (writes fp32 h1 + its bf16 split into Ah1/Al1 cols 0-63)
    embed_kernel<<<(NNODES + 255) / 256, 256>>>(x, emb);
    int warpBlocks = (NNODES * 32 + 255) / 256;
    conv1_kernel<<<warpBlocks, 256>>>(w1_rel, w1_root, b1);

    // conv2: aggr(h1) -> split only into Ah1/Al1 cols 64-127; weights; GEMM -> orig (+split)
    agg_csr<2><<<warpBlocks, 256>>>(buf1, 64, 0, Ah1, Al1, 128, 64);
    wsplit_kernel<<<(1024 * 128 + 255) / 256, 256>>>(w2_root, w2_rel, Bhi, Blo, 128, 1024, 64, 0);
    {
        dim3 grid(1024 / 128, (NNODES + 127) / 128);
        gemm_mma<true, true><<<grid, 256, GEMM_SMEM>>>(Ah1, Al1, Bhi, Blo, b2, orig,
                                                       Ahi, Alo, NNODES, 1024, 128);
    }

    // enc: Y = orig @ [we_root | we_rel];
    // latent = lrelu(aggr(Y_rel) + Y_root + be) -> lat fp32 + split (Ahi/Alo stride 512, cols 0-255)
    wsplit_kernel<<<(512 * 1024 + 255) / 256, 256>>>(we_root, we_rel, Bhi, Blo, 1024, 512, 256, 1);
    {
        dim3 grid(512 / 128, (NNODES + 127) / 128);
        gemm_mma<false, false><<<grid, 256, GEMM_SMEM>>>(Ahi, Alo, Bhi, Blo, nullptr, Y,
                                                         nullptr, nullptr, NNODES, 512, 1024);
    }
    agg_csr4<2><<<warpBlocks, 256>>>(Y, 512, 256, lat, 256, 0, Y, 512, 0, be, 1,
                                     Ahi, Alo, 512, 0);

    // fused mean-pool + logits (no atomics; batch sorted)
    pool_logits_kernel<<<NGRAPHS, 256>>>(w_lin, b_lin, logits);

    // dec-prep: aggr(latent) -> split only into Ahi/Alo cols 256-511
    agg_csr4<2><<<warpBlocks, 256>>>(lat, 256, 0, nullptr, 0, 0, nullptr, 0, 0,
                                     nullptr, 0, Ahi, Alo, 512, 256);

    // dec: GEMM -> reconstructed
    wsplit_kernel<<<(1024 * 512 + 255) / 256, 256>>>(wd_root, wd_rel, Bhi, Blo, 512, 1024, 256, 0);
    {
        dim3 grid(1024 / 128, (NNODES + 127) / 128);
        gemm_mma<true, false><<<grid, 256, GEMM_SMEM>>>(Ahi, Alo, Bhi, Blo, bd, recon,
                                                        nullptr, nullptr, NNODES, 1024, 512);
    }
}

// round 13
// speedup vs baseline: 2.9828x; 1.2988x over previous
#include <cuda_runtime.h>
#include <cuda_fp16.h>
#include <cstdint>

#define NNODES  50000
#define NEDGES  800000
#define NGRAPHS 256
#define SLOPE   0.01f

// ---------------- device scratch (no allocations allowed) ----------------
__device__ int   g_deg[NNODES];
__device__ int   g_fill[NNODES];
__device__ int   g_rowptr[NNODES + 1];
__device__ int   g_esrc[NEDGES];
__device__ int   g_gstart[NGRAPHS + 1];
__device__ __align__(16) float g_buf1[(size_t)NNODES * 64];    // h1 (fp32, agg source)
__device__ __align__(16) float g_Y[(size_t)NNODES * 512];      // cols 0-255: Y_root, 256-511: Y_rel
__device__ __align__(16) float g_lat[(size_t)NNODES * 256];    // latent (pool + agg source)
__device__ __align__(16) __half g_Ah1[(size_t)NNODES * 128];   // [h1 | aggr(h1)] split hi
__device__ __align__(16) __half g_Al1[(size_t)NNODES * 128];   // split lo (GEMM1 is 3-pass)
__device__ __align__(16) __half g_Ahi[(size_t)NNODES * 1024];  // orig hi / [lat|aggr] hi (2-pass A)
__device__ __align__(16) __half g_Bhi[1024 * 1024];
__device__ __align__(16) __half g_Blo[1024 * 1024];

__device__ __forceinline__ float lrelu(float v) { return v >= 0.f ? v : SLOPE * v; }

__device__ __forceinline__ void split4h(float4 v, __half* Hi, __half* Lo, size_t oi) {
    __half2 a = __floats2half2_rn(v.x, v.y);
    __half2 b = __floats2half2_rn(v.z, v.w);
    uint2 u;
    u.x = *reinterpret_cast<uint32_t*>(&a);
    u.y = *reinterpret_cast<uint32_t*>(&b);
    *reinterpret_cast<uint2*>(Hi + oi) = u;
    if (Lo) {
        float2 fa = __half22float2(a), fb = __half22float2(b);
        __half2 la = __floats2half2_rn(v.x - fa.x, v.y - fa.y);
        __half2 lb = __floats2half2_rn(v.z - fb.x, v.w - fb.y);
        uint2 ul;
        ul.x = *reinterpret_cast<uint32_t*>(&la);
        ul.y = *reinterpret_cast<uint32_t*>(&lb);
        *reinterpret_cast<uint2*>(Lo + oi) = ul;
    }
}

// ---------------- CSR build ----------------
__global__ void deg_kernel(const int* __restrict__ dst, int E) {
    int i = blockIdx.x * blockDim.x + threadIdx.x;
    if (i < E) atomicAdd(&g_deg[dst[i]], 1);
}

__global__ void scan_kernel() {
    __shared__ int sm[1024];
    const int CH = (NNODES + 1023) / 1024;
    int t = threadIdx.x;
    int base = t * CH;
    int s = 0;
    for (int i = 0; i < CH; i++) {
        int idx = base + i;
        if (idx < NNODES) s += g_deg[idx];
    }
    sm[t] = s;
    __syncthreads();
    for (int off = 1; off < 1024; off <<= 1) {
        int v = (t >= off) ? sm[t - off] : 0;
        __syncthreads();
        sm[t] += v;
        __syncthreads();
    }
    int prefix = (t > 0) ? sm[t - 1] : 0;
    for (int i = 0; i < CH; i++) {
        int idx = base + i;
        if (idx < NNODES) {
            g_rowptr[idx] = prefix;
            prefix += g_deg[idx];
        }
    }
    if (t == 0) g_rowptr[NNODES] = sm[1023];
}

__global__ void fill_kernel(const int* __restrict__ src, const int* __restrict__ dst, int E) {
    int i = blockIdx.x * blockDim.x + threadIdx.x;
    if (i < E) {
        int d = dst[i];
        int pos = atomicAdd(&g_fill[d], 1);
        g_esrc[g_rowptr[d] + pos] = src[i];
    }
}

// ---------------- graph segment boundaries (batch is sorted) ----------------
__global__ void bounds_kernel(const int* __restrict__ batch) {
    int n = blockIdx.x * blockDim.x + threadIdx.x;
    if (n >= NNODES) return;
    int bn = batch[n];
    int bp = (n == 0) ? -1 : batch[n - 1];
    for (int g = bp + 1; g <= bn; g++) g_gstart[g] = n;
    if (n == NNODES - 1)
        for (int g = bn + 1; g <= NGRAPHS; g++) g_gstart[g] = NNODES;
}

// ---------------- conv1 (embedding fused; 3 -> 64; fp32 + fp16 split output) ----------------
__global__ void conv1_kernel(const int* __restrict__ x, const float* __restrict__ emb,
                             const float* __restrict__ w_rel, const float* __restrict__ w_root,
                             const float* __restrict__ b) {
    __shared__ float semb[32];
    if (threadIdx.x < 30) semb[threadIdx.x] = emb[threadIdx.x];
    __syncthreads();
    int gw = (blockIdx.x * blockDim.x + threadIdx.x) >> 5;
    int lane = threadIdx.x & 31;
    if (gw >= NNODES) return;
    float s0 = 0.f, s1 = 0.f, s2 = 0.f;
    int e0 = g_rowptr[gw], e1 = g_rowptr[gw + 1];
    for (int e = e0 + lane; e < e1; e += 32) {
        int l = x[g_esrc[e]] * 3;
        s0 += semb[l]; s1 += semb[l + 1]; s2 += semb[l + 2];
    }
#pragma unroll
    for (int off = 16; off; off >>= 1) {
        s0 += __shfl_xor_sync(0xffffffffu, s0, off);
        s1 += __shfl_xor_sync(0xffffffffu, s1, off);
        s2 += __shfl_xor_sync(0xffffffffu, s2, off);
    }
    int l0 = x[gw] * 3;
    float r0 = semb[l0], r1 = semb[l0 + 1], r2 = semb[l0 + 2];
#pragma unroll
    for (int q = 0; q < 2; q++) {
        int j = lane + 32 * q;
        float t = b[j] + r0 * w_root[j] + r1 * w_root[64 + j] + r2 * w_root[128 + j]
                       + s0 * w_rel[j]  + s1 * w_rel[64 + j]  + s2 * w_rel[128 + j];
        float v = lrelu(t);
        g_buf1[(size_t)gw * 64 + j] = v;
        __half h = __float2half_rn(v);
        g_Ah1[(size_t)gw * 128 + j] = h;
        g_Al1[(size_t)gw * 128 + j] = __float2half_rn(v - __half2float(h));
    }
}

// ---------------- h1 aggregation (64 cols, float2) -> split into Ah1/Al1 cols 64-127 ----------------
__global__ void agg_h1_kernel() {
    int gw = (blockIdx.x * blockDim.x + threadIdx.x) >> 5;
    int lane = threadIdx.x & 31;
    if (gw >= NNODES) return;
    float2 acc = make_float2(0.f, 0.f);
    int e0 = g_rowptr[gw], e1 = g_rowptr[gw + 1];
    int e = e0;
    for (; e + 1 < e1; e += 2) {
        const float2* p0 = reinterpret_cast<const float2*>(g_buf1 + (size_t)g_esrc[e] * 64);
        const float2* p1 = reinterpret_cast<const float2*>(g_buf1 + (size_t)g_esrc[e + 1] * 64);
        float2 a = p0[lane], b2 = p1[lane];
        acc.x += a.x + b2.x; acc.y += a.y + b2.y;
    }
    if (e < e1) {
        const float2* p = reinterpret_cast<const float2*>(g_buf1 + (size_t)g_esrc[e] * 64);
        float2 a = p[lane];
        acc.x += a.x; acc.y += a.y;
    }
    size_t oi = (size_t)gw * 128 + 64 + 2 * lane;
    __half2 h = __floats2half2_rn(acc.x, acc.y);
    *reinterpret_cast<__half2*>(g_Ah1 + oi) = h;
    float2 hf = __half22float2(h);
    *reinterpret_cast<__half2*>(g_Al1 + oi) = __floats2half2_rn(acc.x - hf.x, acc.y - hf.y);
}

// ---------------- float4 warp-per-node CSR aggregation (256-col cases) ----------------
template <int NC4>
__global__ void agg_csr4(const float* __restrict__ X, int ldx, int xoff,
                         float* __restrict__ O, int ldo, int ooff,
                         const float* __restrict__ addY, int ldy, int yoff,
                         const float* __restrict__ bias, int dolrelu,
                         __half* __restrict__ Ohi, __half* __restrict__ Olo,
                         int lds, int soff) {
    int gw = (blockIdx.x * blockDim.x + threadIdx.x) >> 5;
    int lane = threadIdx.x & 31;
    if (gw >= NNODES) return;
    float4 acc[NC4];
#pragma unroll
    for (int c = 0; c < NC4; c++) acc[c] = make_float4(0.f, 0.f, 0.f, 0.f);
    int e0 = g_rowptr[gw], e1 = g_rowptr[gw + 1];
    int e = e0;
    for (; e + 1 < e1; e += 2) {
        const float4* x0 = reinterpret_cast<const float4*>(X + (size_t)g_esrc[e] * ldx + xoff);
        const float4* x1 = reinterpret_cast<const float4*>(X + (size_t)g_esrc[e + 1] * ldx + xoff);
#pragma unroll
        for (int c = 0; c < NC4; c++) {
            float4 a = x0[lane + 32 * c];
            float4 b4 = x1[lane + 32 * c];
            acc[c].x += a.x + b4.x; acc[c].y += a.y + b4.y;
            acc[c].z += a.z + b4.z; acc[c].w += a.w + b4.w;
        }
    }
    if (e < e1) {
        const float4* xr = reinterpret_cast<const float4*>(X + (size_t)g_esrc[e] * ldx + xoff);
#pragma unroll
        for (int c = 0; c < NC4; c++) {
            float4 a = xr[lane + 32 * c];
            acc[c].x += a.x; acc[c].y += a.y; acc[c].z += a.z; acc[c].w += a.w;
        }
    }
#pragma unroll
    for (int c = 0; c < NC4; c++) {
        float4 v = acc[c];
        int colbase = 4 * (lane + 32 * c);
        if (addY) {
            float4 y = *reinterpret_cast<const float4*>(addY + (size_t)gw * ldy + yoff + colbase);
            v.x += y.x; v.y += y.y; v.z += y.z; v.w += y.w;
        }
        if (bias) {
            float4 bb = *reinterpret_cast<const float4*>(bias + colbase);
            v.x += bb.x; v.y += bb.y; v.z += bb.z; v.w += bb.w;
        }
        if (dolrelu) {
            v.x = lrelu(v.x); v.y = lrelu(v.y); v.z = lrelu(v.z); v.w = lrelu(v.w);
        }
        if (O) *reinterpret_cast<float4*>(O + (size_t)gw * ldo + ooff + colbase) = v;
        if (Ohi) split4h(v, Ohi, Olo, (size_t)gw * lds + soff + colbase);
    }
}

// ---------------- weight concat + transpose + split -> Bt[n*K+k] hi/lo ----------------
__global__ void wsplit_kernel(const float* __restrict__ P, const float* __restrict__ Q,
                              __half* __restrict__ Hi, __half* __restrict__ Lo,
                              int K, int N, int split, int mode) {
    int i = blockIdx.x * blockDim.x + threadIdx.x;
    if (i >= N * K) return;
    int n = i / K, k = i % K;
    float v;
    if (mode == 0) v = (k < split) ? P[(size_t)k * N + n] : Q[(size_t)(k - split) * N + n];
    else           v = (n < split) ? P[(size_t)k * split + n] : Q[(size_t)k * (N - split) + (n - split)];
    __half h = __float2half_rn(v);
    Hi[i] = h;
    Lo[i] = __float2half_rn(v - __half2float(h));
}

// ---------------- tensor-core GEMM via fp16 mma.sync, cp.async double-buffered ----------------
// 2-pass (PASS3=false): C = Ah(Bh+Bl)  [A-lo unused]; 3-pass adds Al*Bh.
#define TS_A 40                          // padded smem row stride (half), conflict-free
#define TILE_B (128 * TS_A * 2)          // 10240 bytes per tile
#define STAGE_B (4 * TILE_B)             // 40960 bytes per stage
#define GEMM_SMEM (2 * STAGE_B)          // 81920 bytes

__device__ __forceinline__ uint32_t smem_u32(const void* p) {
    uint32_t a;
    asm("{ .reg .u64 t; cvta.to.shared.u64 t, %1; cvt.u32.u64 %0, t; }" : "=r"(a) : "l"(p));
    return a;
}
__device__ __forceinline__ void cpasync16(uint32_t dst, const void* src, int src_bytes) {
    asm volatile("cp.async.cg.shared.global [%0], [%1], 16, %2;"
                 :: "r"(dst), "l"(src), "r"(src_bytes) : "memory");
}
__device__ __forceinline__ void cp_commit() {
    asm volatile("cp.async.commit_group;" ::: "memory");
}
template <int NLEFT>
__device__ __forceinline__ void cp_wait() {
    asm volatile("cp.async.wait_group %0;" :: "n"(NLEFT) : "memory");
}
__device__ __forceinline__ void ldsm4(uint32_t& r0, uint32_t& r1, uint32_t& r2, uint32_t& r3,
                                      uint32_t addr) {
    asm volatile("ldmatrix.sync.aligned.m8n8.x4.shared.b16 {%0,%1,%2,%3}, [%4];"
                 : "=r"(r0), "=r"(r1), "=r"(r2), "=r"(r3) : "r"(addr));
}
__device__ __forceinline__ void mma16816(float* c, uint32_t a0, uint32_t a1, uint32_t a2,
                                         uint32_t a3, uint32_t b0, uint32_t b1) {
    asm volatile(
        "mma.sync.aligned.m16n8k16.row.col.f32.f16.f16.f32 "
        "{%0,%1,%2,%3}, {%4,%5,%6,%7}, {%8,%9}, {%0,%1,%2,%3};"
        : "+f"(c[0]), "+f"(c[1]), "+f"(c[2]), "+f"(c[3])
        : "r"(a0), "r"(a1), "r"(a2), "r"(a3), "r"(b0), "r"(b1));
}

template <bool PASS3>
__device__ __forceinline__ void gemm_prefetch(
    uint32_t stage_base, const __half* Ahi, const __half* Alo,
    const __half* Bhi, const __half* Blo,
    int bm, int bn, int M, int K, int k0, int tid) {
#pragma unroll
    for (int it = 0; it < 8; it++) {
        int idx = tid + it * 256;      // 0..2047
        int t = idx >> 9;              // tile 0..3
        if (t == 1 && !PASS3) continue;  // A-lo unused in 2-pass
        int r = (idx >> 2) & 127;      // row
        int c = (idx & 3) * 8;         // col (half units)
        uint32_t dst = stage_base + t * TILE_B + (r * TS_A + c) * 2;
        if (t < 2) {
            int gr = bm + r;
            int ok = (gr < M) ? 16 : 0;
            int grc = (gr < M) ? gr : (M - 1);
            const __half* src = (t == 0 ? Ahi : Alo) + (size_t)grc * K + k0 + c;
            cpasync16(dst, src, ok);
        } else {
            int gn = bn + r;   // N multiple of 128
            const __half* src = (t == 2 ? Bhi : Blo) + (size_t)gn * K + k0 + c;
            cpasync16(dst, src, 16);
        }
    }
}

template <bool BIASRELU, bool SPLITOUT, bool PASS3>
__global__ __launch_bounds__(256, 2)
void gemm_mma(const __half* __restrict__ Ahi, const __half* __restrict__ Alo,
              const __half* __restrict__ Bhi, const __half* __restrict__ Blo,
              const float* __restrict__ bias, float* __restrict__ C,
              __half* __restrict__ Chi, int M, int N, int K) {
    extern __shared__ __align__(16) char dynsm[];
    const uint32_t sbase = smem_u32(dynsm);

    const int tid = threadIdx.x, wid = tid >> 5, lane = tid & 31;
    const int bm = blockIdx.y * 128, bn = blockIdx.x * 128;
    const int wm = (wid & 3) * 32;
    const int wn = (wid >> 2) * 64;

    float acc[2][8][4];
#pragma unroll
    for (int mi = 0; mi < 2; mi++)
#pragma unroll
        for (int nj = 0; nj < 8; nj++)
#pragma unroll
            for (int q = 0; q < 4; q++) acc[mi][nj][q] = 0.f;

    const int aRow = wm + (lane & 15);
    const int aColSel = (lane >> 4) * 8;
    const int bMat = lane >> 3, bR = lane & 7;
    const int bRowOff = (bMat >> 1) * 8 + bR;
    const int bColSel = (bMat & 1) * 8;

    const int nch = K / 32;
    gemm_prefetch<PASS3>(sbase, Ahi, Alo, Bhi, Blo, bm, bn, M, K, 0, tid);
    cp_commit();

    for (int ch = 0; ch < nch; ch++) {
        if (ch + 1 < nch) {
            gemm_prefetch<PASS3>(sbase + ((ch + 1) & 1) * STAGE_B, Ahi, Alo, Bhi, Blo,
                                 bm, bn, M, K, (ch + 1) * 32, tid);
            cp_commit();
            cp_wait<1>();
        } else {
            cp_wait<0>();
        }
        __syncthreads();

        const uint32_t st = sbase + (ch & 1) * STAGE_B;
        const uint32_t aBaseH = st, aBaseL = st + TILE_B;
        const uint32_t bBaseH = st + 2 * TILE_B, bBaseL = st + 3 * TILE_B;

#pragma unroll
        for (int ks = 0; ks < 2; ks++) {
            const int kk = ks * 16;
            uint32_t ah[2][4], al[2][4];
#pragma unroll
            for (int mi = 0; mi < 2; mi++) {
                uint32_t off = ((aRow + mi * 16) * TS_A + kk + aColSel) * 2;
                ldsm4(ah[mi][0], ah[mi][1], ah[mi][2], ah[mi][3], aBaseH + off);
                if (PASS3) ldsm4(al[mi][0], al[mi][1], al[mi][2], al[mi][3], aBaseL + off);
            }
#pragma unroll
            for (int nb = 0; nb < 4; nb++) {
                uint32_t off = ((wn + nb * 16 + bRowOff) * TS_A + kk + bColSel) * 2;
                uint32_t bh0, bh1, bh2, bh3, bl0, bl1, bl2, bl3;
                ldsm4(bh0, bh1, bh2, bh3, bBaseH + off);
                ldsm4(bl0, bl1, bl2, bl3, bBaseL + off);
#pragma unroll
                for (int mi = 0; mi < 2; mi++) {
                    mma16816(acc[mi][2 * nb + 0], ah[mi][0], ah[mi][1], ah[mi][2], ah[mi][3], bh0, bh1);
                    mma16816(acc[mi][2 * nb + 1], ah[mi][0], ah[mi][1], ah[mi][2], ah[mi][3], bh2, bh3);
                    mma16816(acc[mi][2 * nb + 0], ah[mi][0], ah[mi][1], ah[mi][2], ah[mi][3], bl0, bl1);
                    mma16816(acc[mi][2 * nb + 1], ah[mi][0], ah[mi][1], ah[mi][2], ah[mi][3], bl2, bl3);
                    if (PASS3) {
                        mma16816(acc[mi][2 * nb + 0], al[mi][0], al[mi][1], al[mi][2], al[mi][3], bh0, bh1);
                        mma16816(acc[mi][2 * nb + 1], al[mi][0], al[mi][1], al[mi][2], al[mi][3], bh2, bh3);
                    }
                }
            }
        }
        __syncthreads();
    }

    const int crow = lane >> 2;
    const int ccol = 2 * (lane & 3);
#pragma unroll
    for (int mi = 0; mi < 2; mi++) {
#pragma unroll
        for (int half = 0; half < 2; half++) {
            int gr = bm + wm + mi * 16 + crow + half * 8;
            if (gr >= M) continue;
#pragma unroll
            for (int nj = 0; nj < 8; nj++) {
                int gc = bn + wn + nj * 8 + ccol;
                float v0 = acc[mi][nj][2 * half + 0];
                float v1 = acc[mi][nj][2 * half + 1];
                if (BIASRELU) {
                    v0 = lrelu(v0 + bias[gc]);
                    v1 = lrelu(v1 + bias[gc + 1]);
                }
                *reinterpret_cast<float2*>(C + (size_t)gr * N + gc) = make_float2(v0, v1);
                if (SPLITOUT)
                    *reinterpret_cast<__half2*>(Chi + (size_t)gr * N + gc) = __floats2half2_rn(v0, v1);
            }
        }
    }
}

// ---------------- fused mean-pool + logits (segmented over sorted batch) ----------------
__global__ void pool_logits_kernel(const float* __restrict__ w_lin,
                                   const float* __restrict__ b_lin, float* __restrict__ out) {
    __shared__ float sp[256];
    int g = blockIdx.x;
    int s = g_gstart[g], e2 = g_gstart[g + 1];
    int c = threadIdx.x;
    float sum = 0.f;
    for (int n = s; n < e2; n++) sum += g_lat[(size_t)n * 256 + c];
    float cnt = (float)(e2 - s);
    if (cnt < 1.f) cnt = 1.f;
    sp[c] = sum / cnt;
    __syncthreads();
    int warp = threadIdx.x >> 5, lane = threadIdx.x & 31;
    if (warp < 7) {
        float t = 0.f;
#pragma unroll
        for (int k = 0; k < 8; k++) {
            int cc = lane + 32 * k;
            t += sp[cc] * w_lin[cc * 7 + warp];
        }
#pragma unroll
        for (int off = 16; off; off >>= 1) t += __shfl_xor_sync(0xffffffffu, t, off);
        if (lane == 0) out[g * 7 + warp] = t + b_lin[warp];
    }
}

// ---------------- launcher ----------------
extern "C" void kernel_launch(void* const* d_in, const int* in_sizes, int n_in,
                              void* d_out, int out_size) {
    const int*   x       = (const int*)d_in[0];
    const int*   ei      = (const int*)d_in[1];
    const int*   batch   = (const int*)d_in[2];
    const float* emb     = (const float*)d_in[3];
    const float* w1_rel  = (const float*)d_in[4];
    const float* w1_root = (const float*)d_in[5];
    const float* b1      = (const float*)d_in[6];
    const float* w2_rel  = (const float*)d_in[7];
    const float* w2_root = (const float*)d_in[8];
    const float* b2      = (const float*)d_in[9];
    const float* we_rel  = (const float*)d_in[10];
    const float* we_root = (const float*)d_in[11];
    const float* be      = (const float*)d_in[12];
    const float* wd_rel  = (const float*)d_in[13];
    const float* wd_root = (const float*)d_in[14];
    const float* bd      = (const float*)d_in[15];
    const float* w_lin   = (const float*)d_in[16];
    const float* b_lin   = (const float*)d_in[17];

    float* out    = (float*)d_out;
    float* logits = out;
    float* recon  = out + (size_t)NGRAPHS * 7;
    float* orig   = recon + (size_t)NNODES * 1024;

    const int E = NEDGES;

    void *pdeg, *pfill, *pbuf1, *pY, *plat, *pAh1, *pAl1, *pAhi, *pBhi, *pBlo;
    cudaGetSymbolAddress(&pdeg, g_deg);
    cudaGetSymbolAddress(&pfill, g_fill);
    cudaGetSymbolAddress(&pbuf1, g_buf1);
    cudaGetSymbolAddress(&pY, g_Y);
    cudaGetSymbolAddress(&plat, g_lat);
    cudaGetSymbolAddress(&pAh1, g_Ah1);
    cudaGetSymbolAddress(&pAl1, g_Al1);
    cudaGetSymbolAddress(&pAhi, g_Ahi);
    cudaGetSymbolAddress(&pBhi, g_Bhi);
    cudaGetSymbolAddress(&pBlo, g_Blo);
    float* buf1 = (float*)pbuf1;
    float* Y    = (float*)pY;
    float* lat  = (float*)plat;
    __half* Ah1 = (__half*)pAh1;
    __half* Al1 = (__half*)pAl1;
    __half* Ahi = (__half*)pAhi;
    __half* Bhi = (__half*)pBhi;
    __half* Blo = (__half*)pBlo;

    cudaFuncSetAttribute(gemm_mma<true, true, true>,    cudaFuncAttributeMaxDynamicSharedMemorySize, GEMM_SMEM);
    cudaFuncSetAttribute(gemm_mma<false, false, false>, cudaFuncAttributeMaxDynamicSharedMemorySize, GEMM_SMEM);
    cudaFuncSetAttribute(gemm_mma<true, false, false>,  cudaFuncAttributeMaxDynamicSharedMemorySize, GEMM_SMEM);

    cudaMemsetAsync(pdeg, 0, NNODES * sizeof(int));
    cudaMemsetAsync(pfill, 0, NNODES * sizeof(int));

    // CSR build (edges grouped by dst) + graph segment bounds
    deg_kernel<<<(E + 255) / 256, 256>>>(ei + E, E);
    scan_kernel<<<1, 1024>>>();
    fill_kernel<<<(E + 255) / 256, 256>>>(ei, ei + E, E);
    bounds_kernel<<<(NNODES + 255) / 256, 256>>>(batch);

    // conv1 (embedding fused; writes fp32 h1 + fp16 split into Ah1/Al1 cols 0-63)
    int warpBlocks = (NNODES * 32 + 255) / 256;
    conv1_kernel<<<warpBlocks, 256>>>(x, emb, w1_rel, w1_root, b1);

    // conv2: aggr(h1) -> split into Ah1/Al1 cols 64-127; weights; 3-pass GEMM -> orig (+hi split)
    agg_h1_kernel<<<warpBlocks, 256>>>();
    wsplit_kernel<<<(1024 * 128 + 255) / 256, 256>>>(w2_root, w2_rel, Bhi, Blo, 128, 1024, 64, 0);
    {
        dim3 grid(1024 / 128, (NNODES + 127) / 128);
        gemm_mma<true, true, true><<<grid, 256, GEMM_SMEM>>>(Ah1, Al1, Bhi, Blo, b2, orig,
                                                             Ahi, NNODES, 1024, 128);
    }

    // enc (2-pass): Y = orig @ [we_root | we_rel];
    // latent = lrelu(aggr(Y_rel) + Y_root + be) -> lat fp32 + hi split (Ahi stride 512, cols 0-255)
    wsplit_kernel<<<(512 * 1024 + 255) / 256, 256>>>(we_root, we_rel, Bhi, Blo, 1024, 512, 256, 1);
    {
        dim3 grid(512 / 128, (NNODES + 127) / 128);
        gemm_mma<false, false, false><<<grid, 256, GEMM_SMEM>>>(Ahi, nullptr, Bhi, Blo, nullptr, Y,
                                                                nullptr, NNODES, 512, 1024);
    }
    agg_csr4<2><<<warpBlocks, 256>>>(Y, 512, 256, lat, 256, 0, Y, 512, 0, be, 1,
                                     Ahi, nullptr, 512, 0);

    // fused mean-pool + logits (no atomics; batch sorted)
    pool_logits_kernel<<<NGRAPHS, 256>>>(w_lin, b_lin, logits);

    // dec-prep: aggr(latent) -> hi split into Ahi cols 256-511
    agg_csr4<2><<<warpBlocks, 256>>>(lat, 256, 0, nullptr, 0, 0, nullptr, 0, 0,
                                     nullptr, 0, Ahi, nullptr, 512, 256);

    // dec (2-pass): GEMM -> reconstructed
    wsplit_kernel<<<(1024 * 512 + 255) / 256, 256>>>(wd_root, wd_rel, Bhi, Blo, 512, 1024, 256, 0);
    {
        dim3 grid(1024 / 128, (NNODES + 127) / 128);
        gemm_mma<true, false, false><<<grid, 256, GEMM_SMEM>>>(Ahi, nullptr, Bhi, Blo, bd, recon,
                                                               nullptr, NNODES, 1024, 512);
    }
}

// round 16
// speedup vs baseline: 3.1195x; 1.0458x over previous
#include <cuda_runtime.h>
#include <cuda_fp16.h>
#include <cstdint>

#define NNODES  50000
#define NEDGES  800000
#define NGRAPHS 256
#define SLOPE   0.01f

// ---------------- device scratch (no allocations allowed) ----------------
__device__ int   g_deg[NNODES];
__device__ int   g_fill[NNODES];
__device__ int   g_rowptr[NNODES + 1];
__device__ int   g_esrc[NEDGES];
__device__ int   g_gstart[NGRAPHS + 1];
__device__ __align__(16) float  g_Y[(size_t)NNODES * 256];     // Y_root (fp32)
__device__ __align__(16) __half g_Yh[(size_t)NNODES * 256];    // Y_rel (fp16)
__device__ __align__(16) float  g_lat[(size_t)NNODES * 256];   // latent fp32 (pool source)
__device__ __align__(16) __half g_Ah1[(size_t)NNODES * 128];   // [h1 | aggr(h1)] split hi
__device__ __align__(16) __half g_Al1[(size_t)NNODES * 128];   // split lo (GEMM1 is 3-pass)
__device__ __align__(16) __half g_Ahi[(size_t)NNODES * 1024];  // orig hi / [lat|aggr] hi
__device__ __align__(16) __half g_Bhi[1024 * 1024];
__device__ __align__(16) __half g_Blo[1024 * 1024];

__device__ __forceinline__ float lrelu(float v) { return v >= 0.f ? v : SLOPE * v; }

// ---------------- CSR build ----------------
__global__ void deg_kernel(const int* __restrict__ dst, int E) {
    int i = blockIdx.x * blockDim.x + threadIdx.x;
    if (i < E) atomicAdd(&g_deg[dst[i]], 1);
}

__global__ void scan_kernel() {
    __shared__ int sm[1024];
    const int CH = (NNODES + 1023) / 1024;
    int t = threadIdx.x;
    int base = t * CH;
    int s = 0;
    for (int i = 0; i < CH; i++) {
        int idx = base + i;
        if (idx < NNODES) s += g_deg[idx];
    }
    sm[t] = s;
    __syncthreads();
    for (int off = 1; off < 1024; off <<= 1) {
        int v = (t >= off) ? sm[t - off] : 0;
        __syncthreads();
        sm[t] += v;
        __syncthreads();
    }
    int prefix = (t > 0) ? sm[t - 1] : 0;
    for (int i = 0; i < CH; i++) {
        int idx = base + i;
        if (idx < NNODES) {
            g_rowptr[idx] = prefix;
            prefix += g_deg[idx];
        }
    }
    if (t == 0) g_rowptr[NNODES] = sm[1023];
}

__global__ void fill_kernel(const int* __restrict__ src, const int* __restrict__ dst, int E) {
    int i = blockIdx.x * blockDim.x + threadIdx.x;
    if (i < E) {
        int d = dst[i];
        int pos = atomicAdd(&g_fill[d], 1);
        g_esrc[g_rowptr[d] + pos] = src[i];
    }
}

// ---------------- graph segment boundaries (batch is sorted) ----------------
__global__ void bounds_kernel(const int* __restrict__ batch) {
    int n = blockIdx.x * blockDim.x + threadIdx.x;
    if (n >= NNODES) return;
    int bn = batch[n];
    int bp = (n == 0) ? -1 : batch[n - 1];
    for (int g = bp + 1; g <= bn; g++) g_gstart[g] = n;
    if (n == NNODES - 1)
        for (int g = bn + 1; g <= NGRAPHS; g++) g_gstart[g] = NNODES;
}

// ---------------- conv1 (embedding fused; 3 -> 64; fp16 hi/lo split output) ----------------
__global__ void conv1_kernel(const int* __restrict__ x, const float* __restrict__ emb,
                             const float* __restrict__ w_rel, const float* __restrict__ w_root,
                             const float* __restrict__ b) {
    __shared__ float semb[32];
    if (threadIdx.x < 30) semb[threadIdx.x] = emb[threadIdx.x];
    __syncthreads();
    int gw = (blockIdx.x * blockDim.x + threadIdx.x) >> 5;
    int lane = threadIdx.x & 31;
    if (gw >= NNODES) return;
    float s0 = 0.f, s1 = 0.f, s2 = 0.f;
    int e0 = g_rowptr[gw], e1 = g_rowptr[gw + 1];
    for (int e = e0 + lane; e < e1; e += 32) {
        int l = x[g_esrc[e]] * 3;
        s0 += semb[l]; s1 += semb[l + 1]; s2 += semb[l + 2];
    }
#pragma unroll
    for (int off = 16; off; off >>= 1) {
        s0 += __shfl_xor_sync(0xffffffffu, s0, off);
        s1 += __shfl_xor_sync(0xffffffffu, s1, off);
        s2 += __shfl_xor_sync(0xffffffffu, s2, off);
    }
    int l0 = x[gw] * 3;
    float r0 = semb[l0], r1 = semb[l0 + 1], r2 = semb[l0 + 2];
#pragma unroll
    for (int q = 0; q < 2; q++) {
        int j = lane + 32 * q;
        float t = b[j] + r0 * w_root[j] + r1 * w_root[64 + j] + r2 * w_root[128 + j]
                       + s0 * w_rel[j]  + s1 * w_rel[64 + j]  + s2 * w_rel[128 + j];
        float v = lrelu(t);
        __half h = __float2half_rn(v);
        g_Ah1[(size_t)gw * 128 + j] = h;
        g_Al1[(size_t)gw * 128 + j] = __float2half_rn(v - __half2float(h));
    }
}

// ---------------- h1 aggregation (fp16 src, 64 cols) -> split into Ah1/Al1 cols 64-127 ----------------
__global__ void agg_h1_kernel() {
    int gw = (blockIdx.x * blockDim.x + threadIdx.x) >> 5;
    int lane = threadIdx.x & 31;
    if (gw >= NNODES) return;
    float ax = 0.f, ay = 0.f;
    int e0 = g_rowptr[gw], e1 = g_rowptr[gw + 1];
    int e = e0;
    for (; e + 3 < e1; e += 4) {
        __half2 v0 = reinterpret_cast<const __half2*>(g_Ah1 + (size_t)g_esrc[e] * 128)[lane];
        __half2 v1 = reinterpret_cast<const __half2*>(g_Ah1 + (size_t)g_esrc[e + 1] * 128)[lane];
        __half2 v2 = reinterpret_cast<const __half2*>(g_Ah1 + (size_t)g_esrc[e + 2] * 128)[lane];
        __half2 v3 = reinterpret_cast<const __half2*>(g_Ah1 + (size_t)g_esrc[e + 3] * 128)[lane];
        float2 f0 = __half22float2(v0), f1 = __half22float2(v1);
        float2 f2 = __half22float2(v2), f3 = __half22float2(v3);
        ax += (f0.x + f1.x) + (f2.x + f3.x);
        ay += (f0.y + f1.y) + (f2.y + f3.y);
    }
    for (; e < e1; e++) {
        __half2 v = reinterpret_cast<const __half2*>(g_Ah1 + (size_t)g_esrc[e] * 128)[lane];
        float2 f = __half22float2(v);
        ax += f.x; ay += f.y;
    }
    size_t oi = (size_t)gw * 128 + 64 + 2 * lane;
    __half2 h = __floats2half2_rn(ax, ay);
    *reinterpret_cast<__half2*>(g_Ah1 + oi) = h;
    float2 hf = __half22float2(h);
    *reinterpret_cast<__half2*>(g_Al1 + oi) = __floats2half2_rn(ax - hf.x, ay - hf.y);
}

// ---------------- fp16 256-col CSR aggregation (one uint4/lane/edge) ----------------
__device__ __forceinline__ void acc8(float* a, uint4 v) {
    __half2 h0 = *reinterpret_cast<__half2*>(&v.x);
    __half2 h1 = *reinterpret_cast<__half2*>(&v.y);
    __half2 h2 = *reinterpret_cast<__half2*>(&v.z);
    __half2 h3 = *reinterpret_cast<__half2*>(&v.w);
    float2 f0 = __half22float2(h0), f1 = __half22float2(h1);
    float2 f2 = __half22float2(h2), f3 = __half22float2(h3);
    a[0] += f0.x; a[1] += f0.y; a[2] += f1.x; a[3] += f1.y;
    a[4] += f2.x; a[5] += f2.y; a[6] += f3.x; a[7] += f3.y;
}

// FULL: out = lrelu(sum + addY + bias) -> Ofp fp32 (stride 256) + Ohi; else hi only.
template <bool FULL>
__global__ void agg256h(const __half* __restrict__ S, int lds_in,
                        const float* __restrict__ addY, const float* __restrict__ bias,
                        float* __restrict__ Ofp,
                        __half* __restrict__ Ohi, int lds_out, int soff) {
    int gw = (blockIdx.x * blockDim.x + threadIdx.x) >> 5;
    int lane = threadIdx.x & 31;
    if (gw >= NNODES) return;
    float a[8];
#pragma unroll
    for (int i = 0; i < 8; i++) a[i] = 0.f;
    int e0 = g_rowptr[gw], e1 = g_rowptr[gw + 1];
    int e = e0;
    for (; e + 3 < e1; e += 4) {
        uint4 v0 = *reinterpret_cast<const uint4*>(S + (size_t)g_esrc[e] * lds_in + 8 * lane);
        uint4 v1 = *reinterpret_cast<const uint4*>(S + (size_t)g_esrc[e + 1] * lds_in + 8 * lane);
        uint4 v2 = *reinterpret_cast<const uint4*>(S + (size_t)g_esrc[e + 2] * lds_in + 8 * lane);
        uint4 v3 = *reinterpret_cast<const uint4*>(S + (size_t)g_esrc[e + 3] * lds_in + 8 * lane);
        acc8(a, v0); acc8(a, v1); acc8(a, v2); acc8(a, v3);
    }
    for (; e < e1; e++) {
        uint4 v = *reinterpret_cast<const uint4*>(S + (size_t)g_esrc[e] * lds_in + 8 * lane);
        acc8(a, v);
    }
    int cb = 8 * lane;
    if (FULL) {
        float4 y0 = *reinterpret_cast<const float4*>(addY + (size_t)gw * 256 + cb);
        float4 y1 = *reinterpret_cast<const float4*>(addY + (size_t)gw * 256 + cb + 4);
        float4 b0 = *reinterpret_cast<const float4*>(bias + cb);
        float4 b1 = *reinterpret_cast<const float4*>(bias + cb + 4);
        a[0] = lrelu(a[0] + y0.x + b0.x); a[1] = lrelu(a[1] + y0.y + b0.y);
        a[2] = lrelu(a[2] + y0.z + b0.z); a[3] = lrelu(a[3] + y0.w + b0.w);
        a[4] = lrelu(a[4] + y1.x + b1.x); a[5] = lrelu(a[5] + y1.y + b1.y);
        a[6] = lrelu(a[6] + y1.z + b1.z); a[7] = lrelu(a[7] + y1.w + b1.w);
        *reinterpret_cast<float4*>(Ofp + (size_t)gw * 256 + cb) = make_float4(a[0], a[1], a[2], a[3]);
        *reinterpret_cast<float4*>(Ofp + (size_t)gw * 256 + cb + 4) = make_float4(a[4], a[5], a[6], a[7]);
    }
    __half2 h0 = __floats2half2_rn(a[0], a[1]);
    __half2 h1 = __floats2half2_rn(a[2], a[3]);
    __half2 h2 = __floats2half2_rn(a[4], a[5]);
    __half2 h3 = __floats2half2_rn(a[6], a[7]);
    uint4 u;
    u.x = *reinterpret_cast<uint32_t*>(&h0); u.y = *reinterpret_cast<uint32_t*>(&h1);
    u.z = *reinterpret_cast<uint32_t*>(&h2); u.w = *reinterpret_cast<uint32_t*>(&h3);
    *reinterpret_cast<uint4*>(Ohi + (size_t)gw * lds_out + soff + cb) = u;
}

// ---------------- weight concat + transpose + split -> Bt[n*K+k] hi/lo ----------------
__global__ void wsplit_kernel(const float* __restrict__ P, const float* __restrict__ Q,
                              __half* __restrict__ Hi, __half* __restrict__ Lo,
                              int K, int N, int split, int mode) {
    int i = blockIdx.x * blockDim.x + threadIdx.x;
    if (i >= N * K) return;
    int n = i / K, k = i % K;
    float v;
    if (mode == 0) v = (k < split) ? P[(size_t)k * N + n] : Q[(size_t)(k - split) * N + n];
    else           v = (n < split) ? P[(size_t)k * split + n] : Q[(size_t)k * (N - split) + (n - split)];
    __half h = __float2half_rn(v);
    Hi[i] = h;
    Lo[i] = __float2half_rn(v - __half2float(h));
}

// ---------------- tensor-core GEMM via fp16 mma.sync, cp.async double-buffered ----------------
// OMODE 0: C fp32 (stride N). OMODE 1: C fp32 + Chi fp16 (both stride N).
// OMODE 2: gc<256 -> C fp32 (stride 256); gc>=256 -> Chi fp16 (stride 256, col gc-256).
#define TS_A 40
#define TILE_B (128 * TS_A * 2)
#define STAGE_B (4 * TILE_B)
#define GEMM_SMEM (2 * STAGE_B)

__device__ __forceinline__ uint32_t smem_u32(const void* p) {
    uint32_t a;
    asm("{ .reg .u64 t; cvta.to.shared.u64 t, %1; cvt.u32.u64 %0, t; }" : "=r"(a) : "l"(p));
    return a;
}
__device__ __forceinline__ void cpasync16(uint32_t dst, const void* src, int src_bytes) {
    asm volatile("cp.async.cg.shared.global [%0], [%1], 16, %2;"
                 :: "r"(dst), "l"(src), "r"(src_bytes) : "memory");
}
__device__ __forceinline__ void cp_commit() {
    asm volatile("cp.async.commit_group;" ::: "memory");
}
template <int NLEFT>
__device__ __forceinline__ void cp_wait() {
    asm volatile("cp.async.wait_group %0;" :: "n"(NLEFT) : "memory");
}
__device__ __forceinline__ void ldsm4(uint32_t& r0, uint32_t& r1, uint32_t& r2, uint32_t& r3,
                                      uint32_t addr) {
    asm volatile("ldmatrix.sync.aligned.m8n8.x4.shared.b16 {%0,%1,%2,%3}, [%4];"
                 : "=r"(r0), "=r"(r1), "=r"(r2), "=r"(r3) : "r"(addr));
}
__device__ __forceinline__ void mma16816(float* c, uint32_t a0, uint32_t a1, uint32_t a2,
                                         uint32_t a3, uint32_t b0, uint32_t b1) {
    asm volatile(
        "mma.sync.aligned.m16n8k16.row.col.f32.f16.f16.f32 "
        "{%0,%1,%2,%3}, {%4,%5,%6,%7}, {%8,%9}, {%0,%1,%2,%3};"
        : "+f"(c[0]), "+f"(c[1]), "+f"(c[2]), "+f"(c[3])
        : "r"(a0), "r"(a1), "r"(a2), "r"(a3), "r"(b0), "r"(b1));
}

template <bool PASS3>
__device__ __forceinline__ void gemm_prefetch(
    uint32_t stage_base, const __half* Ahi, const __half* Alo,
    const __half* Bhi, const __half* Blo,
    int bm, int bn, int M, int K, int k0, int tid) {
#pragma unroll
    for (int it = 0; it < 8; it++) {
        int idx = tid + it * 256;
        int t = idx >> 9;
        if (t == 1 && !PASS3) continue;
        int r = (idx >> 2) & 127;
        int c = (idx & 3) * 8;
        uint32_t dst = stage_base + t * TILE_B + (r * TS_A + c) * 2;
        if (t < 2) {
            int gr = bm + r;
            int ok = (gr < M) ? 16 : 0;
            int grc = (gr < M) ? gr : (M - 1);
            const __half* src = (t == 0 ? Ahi : Alo) + (size_t)grc * K + k0 + c;
            cpasync16(dst, src, ok);
        } else {
            int gn = bn + r;
            const __half* src = (t == 2 ? Bhi : Blo) + (size_t)gn * K + k0 + c;
            cpasync16(dst, src, 16);
        }
    }
}

template <bool BIASRELU, int OMODE, bool PASS3>
__global__ __launch_bounds__(256, 2)
void gemm_mma(const __half* __restrict__ Ahi, const __half* __restrict__ Alo,
              const __half* __restrict__ Bhi, const __half* __restrict__ Blo,
              const float* __restrict__ bias, float* __restrict__ C,
              __half* __restrict__ Chi, int M, int N, int K) {
    extern __shared__ __align__(16) char dynsm[];
    const uint32_t sbase = smem_u32(dynsm);

    const int tid = threadIdx.x, wid = tid >> 5, lane = tid & 31;
    const int bm = blockIdx.y * 128, bn = blockIdx.x * 128;
    const int wm = (wid & 3) * 32;
    const int wn = (wid >> 2) * 64;

    float acc[2][8][4];
#pragma unroll
    for (int mi = 0; mi < 2; mi++)
#pragma unroll
        for (int nj = 0; nj < 8; nj++)
#pragma unroll
            for (int q = 0; q < 4; q++) acc[mi][nj][q] = 0.f;

    const int aRow = wm + (lane & 15);
    const int aColSel = (lane >> 4) * 8;
    const int bMat = lane >> 3, bR = lane & 7;
    const int bRowOff = (bMat >> 1) * 8 + bR;
    const int bColSel = (bMat & 1) * 8;

    const int nch = K / 32;
    gemm_prefetch<PASS3>(sbase, Ahi, Alo, Bhi, Blo, bm, bn, M, K, 0, tid);
    cp_commit();

    for (int ch = 0; ch < nch; ch++) {
        if (ch + 1 < nch) {
            gemm_prefetch<PASS3>(sbase + ((ch + 1) & 1) * STAGE_B, Ahi, Alo, Bhi, Blo,
                                 bm, bn, M, K, (ch + 1) * 32, tid);
            cp_commit();
            cp_wait<1>();
        } else {
            cp_wait<0>();
        }
        __syncthreads();

        const uint32_t st = sbase + (ch & 1) * STAGE_B;
        const uint32_t aBaseH = st, aBaseL = st + TILE_B;
        const uint32_t bBaseH = st + 2 * TILE_B, bBaseL = st + 3 * TILE_B;

#pragma unroll
        for (int ks = 0; ks < 2; ks++) {
            const int kk = ks * 16;
            uint32_t ah[2][4], al[2][4];
#pragma unroll
            for (int mi = 0; mi < 2; mi++) {
                uint32_t off = ((aRow + mi * 16) * TS_A + kk + aColSel) * 2;
                ldsm4(ah[mi][0], ah[mi][1], ah[mi][2], ah[mi][3], aBaseH + off);
                if (PASS3) ldsm4(al[mi][0], al[mi][1], al[mi][2], al[mi][3], aBaseL + off);
            }
#pragma unroll
            for (int nb = 0; nb < 4; nb++) {
                uint32_t off = ((wn + nb * 16 + bRowOff) * TS_A + kk + bColSel) * 2;
                uint32_t bh0, bh1, bh2, bh3, bl0, bl1, bl2, bl3;
                ldsm4(bh0, bh1, bh2, bh3, bBaseH + off);
                ldsm4(bl0, bl1, bl2, bl3, bBaseL + off);
#pragma unroll
                for (int mi = 0; mi < 2; mi++) {
                    mma16816(acc[mi][2 * nb + 0], ah[mi][0], ah[mi][1], ah[mi][2], ah[mi][3], bh0, bh1);
                    mma16816(acc[mi][2 * nb + 1], ah[mi][0], ah[mi][1], ah[mi][2], ah[mi][3], bh2, bh3);
                    mma16816(acc[mi][2 * nb + 0], ah[mi][0], ah[mi][1], ah[mi][2], ah[mi][3], bl0, bl1);
                    mma16816(acc[mi][2 * nb + 1], ah[mi][0], ah[mi][1], ah[mi][2], ah[mi][3], bl2, bl3);
                    if (PASS3) {
                        mma16816(acc[mi][2 * nb + 0], al[mi][0], al[mi][1], al[mi][2], al[mi][3], bh0, bh1);
                        mma16816(acc[mi][2 * nb + 1], al[mi][0], al[mi][1], al[mi][2], al[mi][3], bh2, bh3);
                    }
                }
            }
        }
        __syncthreads();
    }

    const int crow = lane >> 2;
    const int ccol = 2 * (lane & 3);
#pragma unroll
    for (int mi = 0; mi < 2; mi++) {
#pragma unroll
        for (int half = 0; half < 2; half++) {
            int gr = bm + wm + mi * 16 + crow + half * 8;
            if (gr >= M) continue;
#pragma unroll
            for (int nj = 0; nj < 8; nj++) {
                int gc = bn + wn + nj * 8 + ccol;
                float v0 = acc[mi][nj][2 * half + 0];
                float v1 = acc[mi][nj][2 * half + 1];
                if (BIASRELU) {
                    v0 = lrelu(v0 + bias[gc]);
                    v1 = lrelu(v1 + bias[gc + 1]);
                }
                if (OMODE == 2) {
                    if (gc < 256)
                        *reinterpret_cast<float2*>(C + (size_t)gr * 256 + gc) = make_float2(v0, v1);
                    else
                        *reinterpret_cast<__half2*>(Chi + (size_t)gr * 256 + (gc - 256)) =
                            __floats2half2_rn(v0, v1);
                } else {
                    *reinterpret_cast<float2*>(C + (size_t)gr * N + gc) = make_float2(v0, v1);
                    if (OMODE == 1)
                        *reinterpret_cast<__half2*>(Chi + (size_t)gr * N + gc) = __floats2half2_rn(v0, v1);
                }
            }
        }
    }
}

// ---------------- fused mean-pool + logits (segmented over sorted batch) ----------------
__global__ void pool_logits_kernel(const float* __restrict__ w_lin,
                                   const float* __restrict__ b_lin, float* __restrict__ out) {
    __shared__ float sp[256];
    int g = blockIdx.x;
    int s = g_gstart[g], e2 = g_gstart[g + 1];
    int c = threadIdx.x;
    float sum = 0.f;
    for (int n = s; n < e2; n++) sum += g_lat[(size_t)n * 256 + c];
    float cnt = (float)(e2 - s);
    if (cnt < 1.f) cnt = 1.f;
    sp[c] = sum / cnt;
    __syncthreads();
    int warp = threadIdx.x >> 5, lane = threadIdx.x & 31;
    if (warp < 7) {
        float t = 0.f;
#pragma unroll
        for (int k = 0; k < 8; k++) {
            int cc = lane + 32 * k;
            t += sp[cc] * w_lin[cc * 7 + warp];
        }
#pragma unroll
        for (int off = 16; off; off >>= 1) t += __shfl_xor_sync(0xffffffffu, t, off);
        if (lane == 0) out[g * 7 + warp] = t + b_lin[warp];
    }
}

// ---------------- launcher ----------------
extern "C" void kernel_launch(void* const* d_in, const int* in_sizes, int n_in,
                              void* d_out, int out_size) {
    const int*   x       = (const int*)d_in[0];
    const int*   ei      = (const int*)d_in[1];
    const int*   batch   = (const int*)d_in[2];
    const float* emb     = (const float*)d_in[3];
    const float* w1_rel  = (const float*)d_in[4];
    const float* w1_root = (const float*)d_in[5];
    const float* b1      = (const float*)d_in[6];
    const float* w2_rel  = (const float*)d_in[7];
    const float* w2_root = (const float*)d_in[8];
    const float* b2      = (const float*)d_in[9];
    const float* we_rel  = (const float*)d_in[10];
    const float* we_root = (const float*)d_in[11];
    const float* be      = (const float*)d_in[12];
    const float* wd_rel  = (const float*)d_in[13];
    const float* wd_root = (const float*)d_in[14];
    const float* bd      = (const float*)d_in[15];
    const float* w_lin   = (const float*)d_in[16];
    const float* b_lin   = (const float*)d_in[17];

    float* out    = (float*)d_out;
    float* logits = out;
    float* recon  = out + (size_t)NGRAPHS * 7;
    float* orig   = recon + (size_t)NNODES * 1024;

    const int E = NEDGES;

    void *pdeg, *pfill, *pY, *pYh, *plat, *pAh1, *pAl1, *pAhi, *pBhi, *pBlo;
    cudaGetSymbolAddress(&pdeg, g_deg);
    cudaGetSymbolAddress(&pfill, g_fill);
    cudaGetSymbolAddress(&pY, g_Y);
    cudaGetSymbolAddress(&pYh, g_Yh);
    cudaGetSymbolAddress(&plat, g_lat);
    cudaGetSymbolAddress(&pAh1, g_Ah1);
    cudaGetSymbolAddress(&pAl1, g_Al1);
    cudaGetSymbolAddress(&pAhi, g_Ahi);
    cudaGetSymbolAddress(&pBhi, g_Bhi);
    cudaGetSymbolAddress(&pBlo, g_Blo);
    float* Y    = (float*)pY;
    __half* Yh  = (__half*)pYh;
    float* lat  = (float*)plat;
    __half* Ah1 = (__half*)pAh1;
    __half* Al1 = (__half*)pAl1;
    __half* Ahi = (__half*)pAhi;
    __half* Bhi = (__half*)pBhi;
    __half* Blo = (__half*)pBlo;

    cudaFuncSetAttribute(gemm_mma<true, 1, true>,   cudaFuncAttributeMaxDynamicSharedMemorySize, GEMM_SMEM);
    cudaFuncSetAttribute(gemm_mma<false, 2, false>, cudaFuncAttributeMaxDynamicSharedMemorySize, GEMM_SMEM);
    cudaFuncSetAttribute(gemm_mma<true, 0, false>,  cudaFuncAttributeMaxDynamicSharedMemorySize, GEMM_SMEM);

    cudaMemsetAsync(pdeg, 0, NNODES * sizeof(int));
    cudaMemsetAsync(pfill, 0, NNODES * sizeof(int));

    // CSR build (edges grouped by dst) + graph segment bounds
    deg_kernel<<<(E + 255) / 256, 256>>>(ei + E, E);
    scan_kernel<<<1, 1024>>>();
    fill_kernel<<<(E + 255) / 256, 256>>>(ei, ei + E, E);
    bounds_kernel<<<(NNODES + 255) / 256, 256>>>(batch);

    // conv1 (embedding fused; fp16 split into Ah1/Al1 cols 0-63)
    int warpBlocks = (NNODES * 32 + 255) / 256;
    conv1_kernel<<<warpBlocks, 256>>>(x, emb, w1_rel, w1_root, b1);

    // conv2: aggr(h1) fp16 -> Ah1/Al1 cols 64-127; weights; 3-pass GEMM -> orig fp32 + hi (Ahi)
    agg_h1_kernel<<<warpBlocks, 256>>>();
    wsplit_kernel<<<(1024 * 128 + 255) / 256, 256>>>(w2_root, w2_rel, Bhi, Blo, 128, 1024, 64, 0);
    {
        dim3 grid(1024 / 128, (NNODES + 127) / 128);
        gemm_mma<true, 1, true><<<grid, 256, GEMM_SMEM>>>(Ah1, Al1, Bhi, Blo, b2, orig,
                                                          Ahi, NNODES, 1024, 128);
    }

    // enc (2-pass): Y_root fp32 -> g_Y, Y_rel fp16 -> g_Yh;
    // latent = lrelu(aggr_f16(Y_rel) + Y_root + be) -> lat fp32 + hi (Ahi stride 512, cols 0-255)
    wsplit_kernel<<<(512 * 1024 + 255) / 256, 256>>>(we_root, we_rel, Bhi, Blo, 1024, 512, 256, 1);
    {
        dim3 grid(512 / 128, (NNODES + 127) / 128);
        gemm_mma<false, 2, false><<<grid, 256, GEMM_SMEM>>>(Ahi, nullptr, Bhi, Blo, nullptr, Y,
                                                            Yh, NNODES, 512, 1024);
    }
    agg256h<true><<<warpBlocks, 256>>>(Yh, 256, Y, be, lat, Ahi, 512, 0);

    // fused mean-pool + logits (no atomics; batch sorted)
    pool_logits_kernel<<<NGRAPHS, 256>>>(w_lin, b_lin, logits);

    // dec-prep: aggr_f16(latent hi) -> Ahi cols 256-511
    agg256h<false><<<warpBlocks, 256>>>(Ahi, 512, nullptr, nullptr, nullptr, Ahi, 512, 256);

    // dec (2-pass): GEMM -> reconstructed
    wsplit_kernel<<<(1024 * 512 + 255) / 256, 256>>>(wd_root, wd_rel, Bhi, Blo, 512, 1024, 256, 0);
    {
        dim3 grid(1024 / 128, (NNODES + 127) / 128);
        gemm_mma<true, 0, false><<<grid, 256, GEMM_SMEM>>>(Ahi, nullptr, Bhi, Blo, bd, recon,
                                                           nullptr, NNODES, 1024, 512);
    }
}

// round 17
// speedup vs baseline: 3.1662x; 1.0150x over previous
#include <cuda_runtime.h>
#include <cuda_fp16.h>
#include <cstdint>

#define NNODES  50000
#define NEDGES  800000
#define NGRAPHS 256
#define SLOPE   0.01f

// ---------------- device scratch (no allocations allowed) ----------------
__device__ int   g_cnt[2 * NNODES];          // [0..N): deg, [N..2N): fill cursor
__device__ int   g_rowptr[NNODES + 1];
__device__ int   g_esrc[NEDGES];
__device__ int   g_gstart[NGRAPHS + 1];
__device__ __align__(16) float  g_Y[(size_t)NNODES * 256];     // Y_root (fp32)
__device__ __align__(16) __half g_Yh[(size_t)NNODES * 256];    // Y_rel (fp16)
__device__ __align__(16) __half g_Ah1[(size_t)NNODES * 128];   // [h1 | aggr(h1)] split hi
__device__ __align__(16) __half g_Al1[(size_t)NNODES * 128];   // split lo (GEMM1 is 3-pass)
__device__ __align__(16) __half g_Ahi[(size_t)NNODES * 1024];  // orig hi / [lat|aggr] hi
__device__ __align__(16) __half g_Bhi[1024 * 1024];
__device__ __align__(16) __half g_Blo[1024 * 1024];

__device__ __forceinline__ float lrelu(float v) { return v >= 0.f ? v : SLOPE * v; }

// ---------------- CSR build ----------------
__global__ void deg_kernel(const int* __restrict__ dst, int E) {
    int i = blockIdx.x * blockDim.x + threadIdx.x;
    if (i < E) atomicAdd(&g_cnt[dst[i]], 1);
}

__global__ void scan_kernel() {
    __shared__ int sm[1024];
    const int CH = (NNODES + 1023) / 1024;
    int t = threadIdx.x;
    int base = t * CH;
    int s = 0;
    for (int i = 0; i < CH; i++) {
        int idx = base + i;
        if (idx < NNODES) s += g_cnt[idx];
    }
    sm[t] = s;
    __syncthreads();
    for (int off = 1; off < 1024; off <<= 1) {
        int v = (t >= off) ? sm[t - off] : 0;
        __syncthreads();
        sm[t] += v;
        __syncthreads();
    }
    int prefix = (t > 0) ? sm[t - 1] : 0;
    for (int i = 0; i < CH; i++) {
        int idx = base + i;
        if (idx < NNODES) {
            g_rowptr[idx] = prefix;
            prefix += g_cnt[idx];
        }
    }
    if (t == 0) g_rowptr[NNODES] = sm[1023];
}

__global__ void fill_kernel(const int* __restrict__ src, const int* __restrict__ dst, int E) {
    int i = blockIdx.x * blockDim.x + threadIdx.x;
    if (i < E) {
        int d = dst[i];
        int pos = atomicAdd(&g_cnt[NNODES + d], 1);
        g_esrc[g_rowptr[d] + pos] = src[i];
    }
}

// ---------------- graph segment boundaries (batch is sorted) ----------------
__global__ void bounds_kernel(const int* __restrict__ batch) {
    int n = blockIdx.x * blockDim.x + threadIdx.x;
    if (n >= NNODES) return;
    int bn = batch[n];
    int bp = (n == 0) ? -1 : batch[n - 1];
    for (int g = bp + 1; g <= bn; g++) g_gstart[g] = n;
    if (n == NNODES - 1)
        for (int g = bn + 1; g <= NGRAPHS; g++) g_gstart[g] = NNODES;
}

// ---------------- conv1 (embedding fused; 3 -> 64; fp16 hi/lo split output) ----------------
__global__ void conv1_kernel(const int* __restrict__ x, const float* __restrict__ emb,
                             const float* __restrict__ w_rel, const float* __restrict__ w_root,
                             const float* __restrict__ b) {
    __shared__ float semb[32];
    if (threadIdx.x < 30) semb[threadIdx.x] = emb[threadIdx.x];
    __syncthreads();
    int gw = (blockIdx.x * blockDim.x + threadIdx.x) >> 5;
    int lane = threadIdx.x & 31;
    if (gw >= NNODES) return;
    float s0 = 0.f, s1 = 0.f, s2 = 0.f;
    int e0 = g_rowptr[gw], e1 = g_rowptr[gw + 1];
    for (int e = e0 + lane; e < e1; e += 32) {
        int l = x[g_esrc[e]] * 3;
        s0 += semb[l]; s1 += semb[l + 1]; s2 += semb[l + 2];
    }
#pragma unroll
    for (int off = 16; off; off >>= 1) {
        s0 += __shfl_xor_sync(0xffffffffu, s0, off);
        s1 += __shfl_xor_sync(0xffffffffu, s1, off);
        s2 += __shfl_xor_sync(0xffffffffu, s2, off);
    }
    int l0 = x[gw] * 3;
    float r0 = semb[l0], r1 = semb[l0 + 1], r2 = semb[l0 + 2];
#pragma unroll
    for (int q = 0; q < 2; q++) {
        int j = lane + 32 * q;
        float t = b[j] + r0 * w_root[j] + r1 * w_root[64 + j] + r2 * w_root[128 + j]
                       + s0 * w_rel[j]  + s1 * w_rel[64 + j]  + s2 * w_rel[128 + j];
        float v = lrelu(t);
        __half h = __float2half_rn(v);
        g_Ah1[(size_t)gw * 128 + j] = h;
        g_Al1[(size_t)gw * 128 + j] = __float2half_rn(v - __half2float(h));
    }
}

// ---------------- h1 aggregation (fp16 src, 64 cols) -> split into Ah1/Al1 cols 64-127 ----------------
__global__ void agg_h1_kernel() {
    int gw = (blockIdx.x * blockDim.x + threadIdx.x) >> 5;
    int lane = threadIdx.x & 31;
    if (gw >= NNODES) return;
    float ax = 0.f, ay = 0.f;
    int e0 = g_rowptr[gw], e1 = g_rowptr[gw + 1];
    int e = e0;
    for (; e + 7 < e1; e += 8) {
        float2 f[8];
#pragma unroll
        for (int q = 0; q < 8; q++)
            f[q] = __half22float2(
                reinterpret_cast<const __half2*>(g_Ah1 + (size_t)g_esrc[e + q] * 128)[lane]);
#pragma unroll
        for (int q = 0; q < 8; q++) { ax += f[q].x; ay += f[q].y; }
    }
    for (; e < e1; e++) {
        float2 f = __half22float2(
            reinterpret_cast<const __half2*>(g_Ah1 + (size_t)g_esrc[e] * 128)[lane]);
        ax += f.x; ay += f.y;
    }
    size_t oi = (size_t)gw * 128 + 64 + 2 * lane;
    __half2 h = __floats2half2_rn(ax, ay);
    *reinterpret_cast<__half2*>(g_Ah1 + oi) = h;
    float2 hf = __half22float2(h);
    *reinterpret_cast<__half2*>(g_Al1 + oi) = __floats2half2_rn(ax - hf.x, ay - hf.y);
}

// ---------------- fp16 256-col CSR aggregation (one uint4/lane/edge, MLP 8) ----------------
__device__ __forceinline__ void acc8(float* a, uint4 v) {
    __half2 h0 = *reinterpret_cast<__half2*>(&v.x);
    __half2 h1 = *reinterpret_cast<__half2*>(&v.y);
    __half2 h2 = *reinterpret_cast<__half2*>(&v.z);
    __half2 h3 = *reinterpret_cast<__half2*>(&v.w);
    float2 f0 = __half22float2(h0), f1 = __half22float2(h1);
    float2 f2 = __half22float2(h2), f3 = __half22float2(h3);
    a[0] += f0.x; a[1] += f0.y; a[2] += f1.x; a[3] += f1.y;
    a[4] += f2.x; a[5] += f2.y; a[6] += f3.x; a[7] += f3.y;
}

// FULL: out = lrelu(sum + addY + bias) -> hi only (consumers are all fp16); else hi only.
template <bool FULL>
__global__ void agg256h(const __half* __restrict__ S, int lds_in,
                        const float* __restrict__ addY, const float* __restrict__ bias,
                        __half* __restrict__ Ohi, int lds_out, int soff) {
    int gw = (blockIdx.x * blockDim.x + threadIdx.x) >> 5;
    int lane = threadIdx.x & 31;
    if (gw >= NNODES) return;
    float a[8];
#pragma unroll
    for (int i = 0; i < 8; i++) a[i] = 0.f;
    int e0 = g_rowptr[gw], e1 = g_rowptr[gw + 1];
    int e = e0;
    for (; e + 7 < e1; e += 8) {
        uint4 v[8];
#pragma unroll
        for (int q = 0; q < 8; q++)
            v[q] = *reinterpret_cast<const uint4*>(S + (size_t)g_esrc[e + q] * lds_in + 8 * lane);
#pragma unroll
        for (int q = 0; q < 8; q++) acc8(a, v[q]);
    }
    for (; e < e1; e++) {
        uint4 v = *reinterpret_cast<const uint4*>(S + (size_t)g_esrc[e] * lds_in + 8 * lane);
        acc8(a, v);
    }
    int cb = 8 * lane;
    if (FULL) {
        float4 y0 = *reinterpret_cast<const float4*>(addY + (size_t)gw * 256 + cb);
        float4 y1 = *reinterpret_cast<const float4*>(addY + (size_t)gw * 256 + cb + 4);
        float4 b0 = *reinterpret_cast<const float4*>(bias + cb);
        float4 b1 = *reinterpret_cast<const float4*>(bias + cb + 4);
        a[0] = lrelu(a[0] + y0.x + b0.x); a[1] = lrelu(a[1] + y0.y + b0.y);
        a[2] = lrelu(a[2] + y0.z + b0.z); a[3] = lrelu(a[3] + y0.w + b0.w);
        a[4] = lrelu(a[4] + y1.x + b1.x); a[5] = lrelu(a[5] + y1.y + b1.y);
        a[6] = lrelu(a[6] + y1.z + b1.z); a[7] = lrelu(a[7] + y1.w + b1.w);
    }
    __half2 h0 = __floats2half2_rn(a[0], a[1]);
    __half2 h1 = __floats2half2_rn(a[2], a[3]);
    __half2 h2 = __floats2half2_rn(a[4], a[5]);
    __half2 h3 = __floats2half2_rn(a[6], a[7]);
    uint4 u;
    u.x = *reinterpret_cast<uint32_t*>(&h0); u.y = *reinterpret_cast<uint32_t*>(&h1);
    u.z = *reinterpret_cast<uint32_t*>(&h2); u.w = *reinterpret_cast<uint32_t*>(&h3);
    *reinterpret_cast<uint4*>(Ohi + (size_t)gw * lds_out + soff + cb) = u;
}

// ---------------- tiled weight concat + transpose + split -> Bt[n*K+k] hi/lo ----------------
// Tile: 64 k-rows x 32 n-cols; block (32,8). Coalesced reads and __half2 coalesced writes.
// MODE 0 (rows concat): B[k][n] = k<split ? P[k*N+n] : Q[(k-split)*N+n]
// MODE 1 (cols concat): B[k][n] = n<split ? P[k*split+n] : Q[k*(N-split)+(n-split)]
template <int MODE>
__global__ void wsplit_t(const float* __restrict__ P, const float* __restrict__ Q,
                         __half* __restrict__ Hi, __half* __restrict__ Lo,
                         int K, int N, int split) {
    __shared__ float sm[64][33];
    int k0 = blockIdx.x * 64, n0 = blockIdx.y * 32;
    int tx = threadIdx.x, ty = threadIdx.y;
#pragma unroll
    for (int r = 0; r < 8; r++) {
        int k = k0 + ty + r * 8;
        int n = n0 + tx;
        float v;
        if (MODE == 0) v = (k < split) ? P[(size_t)k * N + n] : Q[(size_t)(k - split) * N + n];
        else           v = (n < split) ? P[(size_t)k * split + n]
                                       : Q[(size_t)k * (N - split) + (n - split)];
        sm[ty + r * 8][tx] = v;
    }
    __syncthreads();
#pragma unroll
    for (int r = 0; r < 4; r++) {
        int nl = ty + r * 8;
        float v0 = sm[2 * tx][nl], v1 = sm[2 * tx + 1][nl];
        __half2 h = __floats2half2_rn(v0, v1);
        float2 hf = __half22float2(h);
        __half2 l = __floats2half2_rn(v0 - hf.x, v1 - hf.y);
        size_t oi = (size_t)(n0 + nl) * K + k0 + 2 * tx;
        *reinterpret_cast<__half2*>(Hi + oi) = h;
        *reinterpret_cast<__half2*>(Lo + oi) = l;
    }
}

// ---------------- tensor-core GEMM via fp16 mma.sync, cp.async double-buffered ----------------
// OMODE 0: C fp32 (stride N). OMODE 1: C fp32 + Chi fp16 (both stride N).
// OMODE 2: gc<256 -> C fp32 (stride 256); gc>=256 -> Chi fp16 (stride 256, col gc-256).
#define TS_A 40
#define TILE_B (128 * TS_A * 2)
#define STAGE_B (4 * TILE_B)
#define GEMM_SMEM (2 * STAGE_B)

__device__ __forceinline__ uint32_t smem_u32(const void* p) {
    uint32_t a;
    asm("{ .reg .u64 t; cvta.to.shared.u64 t, %1; cvt.u32.u64 %0, t; }" : "=r"(a) : "l"(p));
    return a;
}
__device__ __forceinline__ void cpasync16(uint32_t dst, const void* src, int src_bytes) {
    asm volatile("cp.async.cg.shared.global [%0], [%1], 16, %2;"
                 :: "r"(dst), "l"(src), "r"(src_bytes) : "memory");
}
__device__ __forceinline__ void cp_commit() {
    asm volatile("cp.async.commit_group;" ::: "memory");
}
template <int NLEFT>
__device__ __forceinline__ void cp_wait() {
    asm volatile("cp.async.wait_group %0;" :: "n"(NLEFT) : "memory");
}
__device__ __forceinline__ void ldsm4(uint32_t& r0, uint32_t& r1, uint32_t& r2, uint32_t& r3,
                                      uint32_t addr) {
    asm volatile("ldmatrix.sync.aligned.m8n8.x4.shared.b16 {%0,%1,%2,%3}, [%4];"
                 : "=r"(r0), "=r"(r1), "=r"(r2), "=r"(r3) : "r"(addr));
}
__device__ __forceinline__ void mma16816(float* c, uint32_t a0, uint32_t a1, uint32_t a2,
                                         uint32_t a3, uint32_t b0, uint32_t b1) {
    asm volatile(
        "mma.sync.aligned.m16n8k16.row.col.f32.f16.f16.f32 "
        "{%0,%1,%2,%3}, {%4,%5,%6,%7}, {%8,%9}, {%0,%1,%2,%3};"
        : "+f"(c[0]), "+f"(c[1]), "+f"(c[2]), "+f"(c[3])
        : "r"(a0), "r"(a1), "r"(a2), "r"(a3), "r"(b0), "r"(b1));
}

template <bool PASS3>
__device__ __forceinline__ void gemm_prefetch(
    uint32_t stage_base, const __half* Ahi, const __half* Alo,
    const __half* Bhi, const __half* Blo,
    int bm, int bn, int M, int K, int k0, int tid) {
#pragma unroll
    for (int it = 0; it < 8; it++) {
        int idx = tid + it * 256;
        int t = idx >> 9;
        if (t == 1 && !PASS3) continue;
        int r = (idx >> 2) & 127;
        int c = (idx & 3) * 8;
        uint32_t dst = stage_base + t * TILE_B + (r * TS_A + c) * 2;
        if (t < 2) {
            int gr = bm + r;
            int ok = (gr < M) ? 16 : 0;
            int grc = (gr < M) ? gr : (M - 1);
            const __half* src = (t == 0 ? Ahi : Alo) + (size_t)grc * K + k0 + c;
            cpasync16(dst, src, ok);
        } else {
            int gn = bn + r;
            const __half* src = (t == 2 ? Bhi : Blo) + (size_t)gn * K + k0 + c;
            cpasync16(dst, src, 16);
        }
    }
}

template <bool BIASRELU, int OMODE, bool PASS3>
__global__ __launch_bounds__(256, 2)
void gemm_mma(const __half* __restrict__ Ahi, const __half* __restrict__ Alo,
              const __half* __restrict__ Bhi, const __half* __restrict__ Blo,
              const float* __restrict__ bias, float* __restrict__ C,
              __half* __restrict__ Chi, int M, int N, int K) {
    extern __shared__ __align__(16) char dynsm[];
    const uint32_t sbase = smem_u32(dynsm);

    const int tid = threadIdx.x, wid = tid >> 5, lane = tid & 31;
    const int bm = blockIdx.y * 128, bn = blockIdx.x * 128;
    const int wm = (wid & 3) * 32;
    const int wn = (wid >> 2) * 64;

    float acc[2][8][4];
#pragma unroll
    for (int mi = 0; mi < 2; mi++)
#pragma unroll
        for (int nj = 0; nj < 8; nj++)
#pragma unroll
            for (int q = 0; q < 4; q++) acc[mi][nj][q] = 0.f;

    const int aRow = wm + (lane & 15);
    const int aColSel = (lane >> 4) * 8;
    const int bMat = lane >> 3, bR = lane & 7;
    const int bRowOff = (bMat >> 1) * 8 + bR;
    const int bColSel = (bMat & 1) * 8;

    const int nch = K / 32;
    gemm_prefetch<PASS3>(sbase, Ahi, Alo, Bhi, Blo, bm, bn, M, K, 0, tid);
    cp_commit();

    for (int ch = 0; ch < nch; ch++) {
        if (ch + 1 < nch) {
            gemm_prefetch<PASS3>(sbase + ((ch + 1) & 1) * STAGE_B, Ahi, Alo, Bhi, Blo,
                                 bm, bn, M, K, (ch + 1) * 32, tid);
            cp_commit();
            cp_wait<1>();
        } else {
            cp_wait<0>();
        }
        __syncthreads();

        const uint32_t st = sbase + (ch & 1) * STAGE_B;
        const uint32_t aBaseH = st, aBaseL = st + TILE_B;
        const uint32_t bBaseH = st + 2 * TILE_B, bBaseL = st + 3 * TILE_B;

#pragma unroll
        for (int ks = 0; ks < 2; ks++) {
            const int kk = ks * 16;
            uint32_t ah[2][4], al[2][4];
#pragma unroll
            for (int mi = 0; mi < 2; mi++) {
                uint32_t off = ((aRow + mi * 16) * TS_A + kk + aColSel) * 2;
                ldsm4(ah[mi][0], ah[mi][1], ah[mi][2], ah[mi][3], aBaseH + off);
                if (PASS3) ldsm4(al[mi][0], al[mi][1], al[mi][2], al[mi][3], aBaseL + off);
            }
#pragma unroll
            for (int nb = 0; nb < 4; nb++) {
                uint32_t off = ((wn + nb * 16 + bRowOff) * TS_A + kk + bColSel) * 2;
                uint32_t bh0, bh1, bh2, bh3, bl0, bl1, bl2, bl3;
                ldsm4(bh0, bh1, bh2, bh3, bBaseH + off);
                ldsm4(bl0, bl1, bl2, bl3, bBaseL + off);
#pragma unroll
                for (int mi = 0; mi < 2; mi++) {
                    mma16816(acc[mi][2 * nb + 0], ah[mi][0], ah[mi][1], ah[mi][2], ah[mi][3], bh0, bh1);
                    mma16816(acc[mi][2 * nb + 1], ah[mi][0], ah[mi][1], ah[mi][2], ah[mi][3], bh2, bh3);
                    mma16816(acc[mi][2 * nb + 0], ah[mi][0], ah[mi][1], ah[mi][2], ah[mi][3], bl0, bl1);
                    mma16816(acc[mi][2 * nb + 1], ah[mi][0], ah[mi][1], ah[mi][2], ah[mi][3], bl2, bl3);
                    if (PASS3) {
                        mma16816(acc[mi][2 * nb + 0], al[mi][0], al[mi][1], al[mi][2], al[mi][3], bh0, bh1);
                        mma16816(acc[mi][2 * nb + 1], al[mi][0], al[mi][1], al[mi][2], al[mi][3], bh2, bh3);
                    }
                }
            }
        }
        __syncthreads();
    }

    const int crow = lane >> 2;
    const int ccol = 2 * (lane & 3);
#pragma unroll
    for (int mi = 0; mi < 2; mi++) {
#pragma unroll
        for (int half = 0; half < 2; half++) {
            int gr = bm + wm + mi * 16 + crow + half * 8;
            if (gr >= M) continue;
#pragma unroll
            for (int nj = 0; nj < 8; nj++) {
                int gc = bn + wn + nj * 8 + ccol;
                float v0 = acc[mi][nj][2 * half + 0];
                float v1 = acc[mi][nj][2 * half + 1];
                if (BIASRELU) {
                    v0 = lrelu(v0 + bias[gc]);
                    v1 = lrelu(v1 + bias[gc + 1]);
                }
                if (OMODE == 2) {
                    if (gc < 256)
                        *reinterpret_cast<float2*>(C + (size_t)gr * 256 + gc) = make_float2(v0, v1);
                    else
                        *reinterpret_cast<__half2*>(Chi + (size_t)gr * 256 + (gc - 256)) =
                            __floats2half2_rn(v0, v1);
                } else {
                    *reinterpret_cast<float2*>(C + (size_t)gr * N + gc) = make_float2(v0, v1);
                    if (OMODE == 1)
                        *reinterpret_cast<__half2*>(Chi + (size_t)gr * N + gc) = __floats2half2_rn(v0, v1);
                }
            }
        }
    }
}

// ---------------- fused mean-pool + logits (fp16 latent from Ahi, stride 512) ----------------
__global__ void pool_logits_kernel(const __half* __restrict__ lat_h,
                                   const float* __restrict__ w_lin,
                                   const float* __restrict__ b_lin, float* __restrict__ out) {
    __shared__ float sp[256];
    int g = blockIdx.x;
    int s = g_gstart[g], e2 = g_gstart[g + 1];
    int c = threadIdx.x;
    float sum = 0.f;
    for (int n = s; n < e2; n++) sum += __half2float(lat_h[(size_t)n * 512 + c]);
    float cnt = (float)(e2 - s);
    if (cnt < 1.f) cnt = 1.f;
    sp[c] = sum / cnt;
    __syncthreads();
    int warp = threadIdx.x >> 5, lane = threadIdx.x & 31;
    if (warp < 7) {
        float t = 0.f;
#pragma unroll
        for (int k = 0; k < 8; k++) {
            int cc = lane + 32 * k;
            t += sp[cc] * w_lin[cc * 7 + warp];
        }
#pragma unroll
        for (int off = 16; off; off >>= 1) t += __shfl_xor_sync(0xffffffffu, t, off);
        if (lane == 0) out[g * 7 + warp] = t + b_lin[warp];
    }
}

// ---------------- launcher ----------------
extern "C" void kernel_launch(void* const* d_in, const int* in_sizes, int n_in,
                              void* d_out, int out_size) {
    const int*   x       = (const int*)d_in[0];
    const int*   ei      = (const int*)d_in[1];
    const int*   batch   = (const int*)d_in[2];
    const float* emb     = (const float*)d_in[3];
    const float* w1_rel  = (const float*)d_in[4];
    const float* w1_root = (const float*)d_in[5];
    const float* b1      = (const float*)d_in[6];
    const float* w2_rel  = (const float*)d_in[7];
    const float* w2_root = (const float*)d_in[8];
    const float* b2      = (const float*)d_in[9];
    const float* we_rel  = (const float*)d_in[10];
    const float* we_root = (const float*)d_in[11];
    const float* be      = (const float*)d_in[12];
    const float* wd_rel  = (const float*)d_in[13];
    const float* wd_root = (const float*)d_in[14];
    const float* bd      = (const float*)d_in[15];
    const float* w_lin   = (const float*)d_in[16];
    const float* b_lin   = (const float*)d_in[17];

    float* out    = (float*)d_out;
    float* logits = out;
    float* recon  = out + (size_t)NGRAPHS * 7;
    float* orig   = recon + (size_t)NNODES * 1024;

    const int E = NEDGES;

    void *pcnt, *pY, *pYh, *pAh1, *pAl1, *pAhi, *pBhi, *pBlo;
    cudaGetSymbolAddress(&pcnt, g_cnt);
    cudaGetSymbolAddress(&pY, g_Y);
    cudaGetSymbolAddress(&pYh, g_Yh);
    cudaGetSymbolAddress(&pAh1, g_Ah1);
    cudaGetSymbolAddress(&pAl1, g_Al1);
    cudaGetSymbolAddress(&pAhi, g_Ahi);
    cudaGetSymbolAddress(&pBhi, g_Bhi);
    cudaGetSymbolAddress(&pBlo, g_Blo);
    float* Y    = (float*)pY;
    __half* Yh  = (__half*)pYh;
    __half* Ah1 = (__half*)pAh1;
    __half* Al1 = (__half*)pAl1;
    __half* Ahi = (__half*)pAhi;
    __half* Bhi = (__half*)pBhi;
    __half* Blo = (__half*)pBlo;

    cudaFuncSetAttribute(gemm_mma<true, 1, true>,   cudaFuncAttributeMaxDynamicSharedMemorySize, GEMM_SMEM);
    cudaFuncSetAttribute(gemm_mma<false, 2, false>, cudaFuncAttributeMaxDynamicSharedMemorySize, GEMM_SMEM);
    cudaFuncSetAttribute(gemm_mma<true, 0, false>,  cudaFuncAttributeMaxDynamicSharedMemorySize, GEMM_SMEM);

    cudaMemsetAsync(pcnt, 0, 2 * NNODES * sizeof(int));

    // CSR build (edges grouped by dst) + graph segment bounds
    deg_kernel<<<(E + 255) / 256, 256>>>(ei + E, E);
    scan_kernel<<<1, 1024>>>();
    fill_kernel<<<(E + 255) / 256, 256>>>(ei, ei + E, E);
    bounds_kernel<<<(NNODES + 255) / 256, 256>>>(batch);

    // conv1 (embedding fused; fp16 split into Ah1/Al1 cols 0-63)
    int warpBlocks = (NNODES * 32 + 255) / 256;
    conv1_kernel<<<warpBlocks, 256>>>(x, emb, w1_rel, w1_root, b1);

    // conv2: aggr(h1) fp16 -> Ah1/Al1 cols 64-127; weights; 3-pass GEMM -> orig fp32 + hi (Ahi)
    agg_h1_kernel<<<warpBlocks, 256>>>();
    {
        dim3 grid(128 / 64, 1024 / 32);
        wsplit_t<0><<<grid, dim3(32, 8)>>>(w2_root, w2_rel, Bhi, Blo, 128, 1024, 64);
    }
    {
        dim3 grid(1024 / 128, (NNODES + 127) / 128);
        gemm_mma<true, 1, true><<<grid, 256, GEMM_SMEM>>>(Ah1, Al1, Bhi, Blo, b2, orig,
                                                          Ahi, NNODES, 1024, 128);
    }

    // enc (2-pass): Y_root fp32 -> g_Y, Y_rel fp16 -> g_Yh;
    // latent = lrelu(aggr_f16(Y_rel) + Y_root + be) -> hi only (Ahi stride 512, cols 0-255)
    {
        dim3 grid(1024 / 64, 512 / 32);
        wsplit_t<1><<<grid, dim3(32, 8)>>>(we_root, we_rel, Bhi, Blo, 1024, 512, 256);
    }
    {
        dim3 grid(512 / 128, (NNODES + 127) / 128);
        gemm_mma<false, 2, false><<<grid, 256, GEMM_SMEM>>>(Ahi, nullptr, Bhi, Blo, nullptr, Y,
                                                            Yh, NNODES, 512, 1024);
    }
    agg256h<true><<<warpBlocks, 256>>>(Yh, 256, Y, be, Ahi, 512, 0);

    // fused mean-pool + logits (fp16 latent; batch sorted)
    pool_logits_kernel<<<NGRAPHS, 256>>>(Ahi, w_lin, b_lin, logits);

    // dec-prep: aggr_f16(latent hi) -> Ahi cols 256-511
    agg256h<false><<<warpBlocks, 256>>>(Ahi, 512, nullptr, nullptr, Ahi, 512, 256);

    // dec (2-pass): GEMM -> reconstructed
    {
        dim3 grid(512 / 64, 1024 / 32);
        wsplit_t<0><<<grid, dim3(32, 8)>>>(wd_root, wd_rel, Bhi, Blo, 512, 1024, 256);
    }
    {
        dim3 grid(1024 / 128, (NNODES + 127) / 128);
        gemm_mma<true, 0, false><<<grid, 256, GEMM_SMEM>>>(Ahi, nullptr, Bhi, Blo, bd, recon,
                                                           nullptr, NNODES, 1024, 512);
    }
}